// round 3
// baseline (speedup 1.0000x reference)
#include <cuda_runtime.h>
#include <math.h>

// ---------------------------------------------------------------------------
// Problem: B=32,T=512,N=4,E=16, NI=16,EI=8, HN=HE=128, MH=256, C=8
// M_node=65536, M_edge=262144
// ---------------------------------------------------------------------------

typedef unsigned long long u64;

#define SPB 5
#define LSTM_SMEM_FLOATS (96*512 + SPB*256 + SPB*128 + SPB*512)
#define LSTM_SMEM_BYTES  (LSTM_SMEM_FLOATS * 4)

// Static scratch (allocation-free rule)
__device__ float g_nA[65536 * 128];
__device__ float g_nB[65536 * 128];
__device__ float g_eA[262144 * 128];
__device__ float g_eB[262144 * 128];
__device__ float g_xzn[65536 * 512];
__device__ float g_xze[134217728];   // 262144 * 512
__device__ float g_c1[67108864];     // 262144 * 256

// ---- packed fp32x2 helpers ----
__device__ __forceinline__ u64 pk2(float lo, float hi) {
    u64 r; asm("mov.b64 %0, {%1,%2};" : "=l"(r) : "f"(lo), "f"(hi)); return r;
}
__device__ __forceinline__ void up2(float& lo, float& hi, u64 v) {
    asm("mov.b64 {%0,%1}, %2;" : "=f"(lo), "=f"(hi) : "l"(v));
}
__device__ __forceinline__ void fma2(u64& c, u64 a, u64 b) {
    asm("fma.rn.f32x2 %0, %1, %2, %0;" : "+l"(c) : "l"(a), "l"(b));
}
__device__ __forceinline__ u64 add2(u64 a, u64 b) {
    u64 r; asm("add.rn.f32x2 %0, %1, %2;" : "=l"(r) : "l"(a), "l"(b)); return r;
}

__device__ __forceinline__ float sigmf(float x) { return 1.0f / (1.0f + __expf(-x)); }
__device__ __forceinline__ float tanhfast(float x) { return 1.0f - 2.0f / (__expf(2.0f * x) + 1.0f); }

// ---------------------------------------------------------------------------
// f32x2 SGEMM (unchanged from round 2 — control)
// ---------------------------------------------------------------------------
template <int RELU, int HASBIAS, int ADJMIX>
__global__ __launch_bounds__(256) void sgemm2(
    const float* __restrict__ A, const float* __restrict__ B,
    const float* __restrict__ bias, float* __restrict__ C,
    int M, int N, int K)
{
    __shared__ float As[16][128];
    __shared__ float Bs[16][128];
    const int tid  = threadIdx.x;
    const int bm   = blockIdx.y * 128;
    const int bn   = blockIdx.x * 128;
    const int arow = tid >> 1;
    const int acol = (tid & 1) * 8;
    const int brow = tid >> 4;
    const int bcol = (tid & 15) * 8;
    const int tx   = (tid & 15) * 8;
    const int ty   = (tid >> 4) * 8;

    const float* Ap = A + (size_t)(bm + arow) * K + acol;
    const float* Bp = B + (size_t)brow * N + bn + bcol;

    float4 a0 = *(const float4*)(Ap);
    float4 a1 = *(const float4*)(Ap + 4);
    float4 b0 = *(const float4*)(Bp);
    float4 b1 = *(const float4*)(Bp + 4);

    u64 acc[4][8];
#pragma unroll
    for (int i = 0; i < 4; i++)
#pragma unroll
        for (int j = 0; j < 8; j++) acc[i][j] = 0ull;

    int k0 = 0;
    for (;;) {
        As[acol + 0][arow] = a0.x; As[acol + 1][arow] = a0.y;
        As[acol + 2][arow] = a0.z; As[acol + 3][arow] = a0.w;
        As[acol + 4][arow] = a1.x; As[acol + 5][arow] = a1.y;
        As[acol + 6][arow] = a1.z; As[acol + 7][arow] = a1.w;
        *(float4*)&Bs[brow][bcol]     = b0;
        *(float4*)&Bs[brow][bcol + 4] = b1;
        __syncthreads();

        k0 += 16;
        bool more = (k0 < K);
        if (more) {
            a0 = *(const float4*)(Ap + k0);
            a1 = *(const float4*)(Ap + k0 + 4);
            b0 = *(const float4*)(Bp + (size_t)k0 * N);
            b1 = *(const float4*)(Bp + (size_t)k0 * N + 4);
        }

#pragma unroll
        for (int kk = 0; kk < 16; kk++) {
            ulonglong2 apA = *(const ulonglong2*)&As[kk][ty];
            ulonglong2 apB = *(const ulonglong2*)&As[kk][ty + 4];
            float4 c0 = *(const float4*)&Bs[kk][tx];
            float4 c1 = *(const float4*)&Bs[kk][tx + 4];
            u64 bd[8];
            bd[0] = pk2(c0.x, c0.x); bd[1] = pk2(c0.y, c0.y);
            bd[2] = pk2(c0.z, c0.z); bd[3] = pk2(c0.w, c0.w);
            bd[4] = pk2(c1.x, c1.x); bd[5] = pk2(c1.y, c1.y);
            bd[6] = pk2(c1.z, c1.z); bd[7] = pk2(c1.w, c1.w);
            u64 ap[4] = { apA.x, apA.y, apB.x, apB.y };
#pragma unroll
            for (int i = 0; i < 4; i++)
#pragma unroll
                for (int j = 0; j < 8; j++)
                    fma2(acc[i][j], ap[i], bd[j]);
        }
        if (!more) break;
        __syncthreads();
    }

    float v[8][8];
#pragma unroll
    for (int i = 0; i < 4; i++)
#pragma unroll
        for (int j = 0; j < 8; j++)
            up2(v[2 * i][j], v[2 * i + 1][j], acc[i][j]);

    float bv[8];
    if (HASBIAS || ADJMIX) {
        *(float4*)&bv[0] = *(const float4*)&bias[bn + tx];
        *(float4*)&bv[4] = *(const float4*)&bias[bn + tx + 4];
    }

    if (ADJMIX) {
#pragma unroll
        for (int g = 0; g < 2; g++) {
            float s[8];
#pragma unroll
            for (int j = 0; j < 8; j++)
                s[j] = v[4*g][j] + v[4*g+1][j] + v[4*g+2][j] + v[4*g+3][j];
#pragma unroll
            for (int r = 0; r < 4; r++) {
                float* Crow = C + (size_t)(bm + ty + 4*g + r) * N + bn + tx;
                float o[8];
#pragma unroll
                for (int j = 0; j < 8; j++)
                    o[j] = fmaxf((s[j] + v[4*g+r][j]) * 0.2f + bv[j], 0.f);
                *(float4*)(Crow)     = make_float4(o[0], o[1], o[2], o[3]);
                *(float4*)(Crow + 4) = make_float4(o[4], o[5], o[6], o[7]);
            }
        }
    } else {
#pragma unroll
        for (int r = 0; r < 8; r++) {
            float* Crow = C + (size_t)(bm + ty + r) * N + bn + tx;
            float o[8];
#pragma unroll
            for (int j = 0; j < 8; j++) {
                o[j] = v[r][j];
                if (HASBIAS) o[j] += bv[j];
                if (RELU)    o[j] = fmaxf(o[j], 0.f);
            }
            *(float4*)(Crow)     = make_float4(o[0], o[1], o[2], o[3]);
            *(float4*)(Crow + 4) = make_float4(o[4], o[5], o[6], o[7]);
        }
    }
}

// ---------------------------------------------------------------------------
// BK=8 SGEMM for K=8 first edge layer (unchanged)
// ---------------------------------------------------------------------------
__global__ __launch_bounds__(256) void sgemm_k8(
    const float* __restrict__ A, const float* __restrict__ B,
    const float* __restrict__ bias, float* __restrict__ C,
    int M, int N, int K)
{
    __shared__ float As[8][128];
    __shared__ float Bs[8][128];
    const int tid  = threadIdx.x;
    const int bm   = blockIdx.y * 128;
    const int bn   = blockIdx.x * 128;
    const int arow = tid >> 1;
    const int acol = (tid & 1) * 4;
    const int brow = tid >> 5;
    const int bcol = (tid & 31) * 4;
    const int tx   = (tid & 15) * 8;
    const int ty   = (tid >> 4) * 8;

    const float* Ab = A + (size_t)(bm + arow) * K + acol;
    const float* Bb = B + (size_t)brow * N + bn + bcol;

    float acc[8][8];
#pragma unroll
    for (int i = 0; i < 8; i++)
#pragma unroll
        for (int j = 0; j < 8; j++) acc[i][j] = 0.f;

    for (int k0 = 0; k0 < K; k0 += 8) {
        float4 av = *(const float4*)(Ab + k0);
        float4 bv = *(const float4*)(Bb + (size_t)k0 * N);
        As[acol + 0][arow] = av.x;
        As[acol + 1][arow] = av.y;
        As[acol + 2][arow] = av.z;
        As[acol + 3][arow] = av.w;
        *(float4*)&Bs[brow][bcol] = bv;
        __syncthreads();
#pragma unroll
        for (int kk = 0; kk < 8; kk++) {
            float ar[8], br[8];
            *(float4*)&ar[0] = *(const float4*)&As[kk][ty];
            *(float4*)&ar[4] = *(const float4*)&As[kk][ty + 4];
            *(float4*)&br[0] = *(const float4*)&Bs[kk][tx];
            *(float4*)&br[4] = *(const float4*)&Bs[kk][tx + 4];
#pragma unroll
            for (int i = 0; i < 8; i++)
#pragma unroll
                for (int j = 0; j < 8; j++)
                    acc[i][j] += ar[i] * br[j];
        }
        __syncthreads();
    }

    float bv_[8];
    *(float4*)&bv_[0] = *(const float4*)&bias[bn + tx];
    *(float4*)&bv_[4] = *(const float4*)&bias[bn + tx + 4];
#pragma unroll
    for (int i = 0; i < 8; i++) {
        float* Crow = C + (size_t)(bm + ty + i) * N + bn + tx;
        float v[8];
#pragma unroll
        for (int j = 0; j < 8; j++)
            v[j] = fmaxf(acc[i][j] + bv_[j], 0.f);
        *(float4*)(Crow)     = make_float4(v[0], v[1], v[2], v[3]);
        *(float4*)(Crow + 4) = make_float4(v[4], v[5], v[6], v[7]);
    }
}

// ---------------------------------------------------------------------------
// Classifier GEMM with fused gather (unchanged)
// ---------------------------------------------------------------------------
__global__ __launch_bounds__(256) void sgemm_c1(
    const float* __restrict__ hn, const float* __restrict__ he,
    const float* __restrict__ Wc1, const float* __restrict__ bc1,
    float* __restrict__ C)
{
    const int N = 256, K = 384;
    __shared__ float As[16][128];
    __shared__ float Bs[16][128];
    const int tid  = threadIdx.x;
    const int bm   = blockIdx.y * 128;
    const int bn   = blockIdx.x * 128;
    const int arow = tid >> 1;
    const int acol = (tid & 1) * 8;
    const int brow = tid >> 4;
    const int bcol = (tid & 15) * 8;
    const int tx   = (tid & 15) * 8;
    const int ty   = (tid >> 4) * 8;

    const int row = bm + arow;
    const int bt  = row >> 4;
    const int e   = row & 15;
    const float* seg0 = hn + ((size_t)bt * 4 + (e >> 2)) * 128 + acol;
    const float* seg1 = hn + ((size_t)bt * 4 + (e & 3)) * 128 + acol;
    const float* seg2 = he + (size_t)row * 128 + acol;

    const float* Bp = Wc1 + (size_t)brow * N + bn + bcol;

    float4 a0 = *(const float4*)(seg0);
    float4 a1 = *(const float4*)(seg0 + 4);
    float4 b0 = *(const float4*)(Bp);
    float4 b1 = *(const float4*)(Bp + 4);

    u64 acc[4][8];
#pragma unroll
    for (int i = 0; i < 4; i++)
#pragma unroll
        for (int j = 0; j < 8; j++) acc[i][j] = 0ull;

    int k0 = 0;
    for (;;) {
        As[acol + 0][arow] = a0.x; As[acol + 1][arow] = a0.y;
        As[acol + 2][arow] = a0.z; As[acol + 3][arow] = a0.w;
        As[acol + 4][arow] = a1.x; As[acol + 5][arow] = a1.y;
        As[acol + 6][arow] = a1.z; As[acol + 7][arow] = a1.w;
        *(float4*)&Bs[brow][bcol]     = b0;
        *(float4*)&Bs[brow][bcol + 4] = b1;
        __syncthreads();

        k0 += 16;
        bool more = (k0 < K);
        if (more) {
            const float* sp = (k0 < 128) ? seg0 : ((k0 < 256) ? seg1 : seg2);
            a0 = *(const float4*)(sp + (k0 & 127));
            a1 = *(const float4*)(sp + (k0 & 127) + 4);
            b0 = *(const float4*)(Bp + (size_t)k0 * N);
            b1 = *(const float4*)(Bp + (size_t)k0 * N + 4);
        }

#pragma unroll
        for (int kk = 0; kk < 16; kk++) {
            ulonglong2 apA = *(const ulonglong2*)&As[kk][ty];
            ulonglong2 apB = *(const ulonglong2*)&As[kk][ty + 4];
            float4 c0 = *(const float4*)&Bs[kk][tx];
            float4 c1 = *(const float4*)&Bs[kk][tx + 4];
            u64 bd[8];
            bd[0] = pk2(c0.x, c0.x); bd[1] = pk2(c0.y, c0.y);
            bd[2] = pk2(c0.z, c0.z); bd[3] = pk2(c0.w, c0.w);
            bd[4] = pk2(c1.x, c1.x); bd[5] = pk2(c1.y, c1.y);
            bd[6] = pk2(c1.z, c1.z); bd[7] = pk2(c1.w, c1.w);
            u64 ap[4] = { apA.x, apA.y, apB.x, apB.y };
#pragma unroll
            for (int i = 0; i < 4; i++)
#pragma unroll
                for (int j = 0; j < 8; j++)
                    fma2(acc[i][j], ap[i], bd[j]);
        }
        if (!more) break;
        __syncthreads();
    }

    float v[8][8];
#pragma unroll
    for (int i = 0; i < 4; i++)
#pragma unroll
        for (int j = 0; j < 8; j++)
            up2(v[2 * i][j], v[2 * i + 1][j], acc[i][j]);

    float bv[8];
    *(float4*)&bv[0] = *(const float4*)&bc1[bn + tx];
    *(float4*)&bv[4] = *(const float4*)&bc1[bn + tx + 4];
#pragma unroll
    for (int r = 0; r < 8; r++) {
        float* Crow = C + (size_t)(bm + ty + r) * N + bn + tx;
        float o[8];
#pragma unroll
        for (int j = 0; j < 8; j++)
            o[j] = fmaxf(v[r][j] + bv[j], 0.f);
        *(float4*)(Crow)     = make_float4(o[0], o[1], o[2], o[3]);
        *(float4*)(Crow + 4) = make_float4(o[4], o[5], o[6], o[7]);
    }
}

// ---------------------------------------------------------------------------
// LSTM v3: 512 threads (16 warps/SM), f32x2, sequences split 3/2 across
// thread halves, xz prefetched one step ahead. nsteps parameterized so the
// same kernel serves as a short diagnostic launch.
// Blocks 0..25: node (128 seqs). Blocks 26..128: edge (512 seqs). SPB=5.
// ---------------------------------------------------------------------------
__global__ __launch_bounds__(512, 1) void lstm3(
    const float* __restrict__ xz_n, const float* __restrict__ Whh_n, float* __restrict__ hn,
    const float* __restrict__ xz_e, const float* __restrict__ Whh_e, float* __restrict__ he,
    int nsteps)
{
    extern __shared__ float sm[];
    float* ws   = sm;                    // 96*512
    float* hdup = ws + 96 * 512;         // SPB*256 (duplicated h)
    float* csm  = hdup + SPB * 256;      // SPB*128
    float* zsm  = csm + SPB * 128;       // SPB*512

    const int tid = threadIdx.x;
    const int sub = tid >> 8;            // 0: seqs 0..2, 1: seqs 3..4
    const int lt  = tid & 255;
    const int c2  = 2 * lt;
    const int i0  = sub ? 3 : 0;
    const int ni  = sub ? 2 : 3;

    const float* Whh;
    const float* xz;
    float* out;
    int seq0, nseq;
    int is_node;

    if (blockIdx.x < 26) {
        Whh = Whh_n; xz = xz_n; out = hn;
        seq0 = blockIdx.x * SPB; nseq = 128; is_node = 1;
    } else {
        Whh = Whh_e; xz = xz_e; out = he;
        seq0 = (blockIdx.x - 26) * SPB; nseq = 512; is_node = 0;
    }
    const long xstep = is_node ? (4 * 512) : (16 * 512);
    const long ostep = is_node ? (4 * 128) : (16 * 128);

    // per-thread xz pointers for its own sequences
    const float* xp[3];
    int valid[3];
#pragma unroll
    for (int j = 0; j < 3; j++) {
        int s = seq0 + i0 + j;
        valid[j] = (j < ni) && (s < nseq);
        long row = is_node ? ((long)(s >> 2) * 2048 + (s & 3))
                           : ((long)(s >> 4) * 8192 + (s & 15));
        xp[j] = xz + row * 512 + c2;
    }

    // Whh rows 0..95 -> SMEM; rows 96..127 -> regs (column-pair u64)
    for (int idx = tid; idx < (96 * 512) / 4; idx += 512)
        ((float4*)ws)[idx] = ((const float4*)Whh)[idx];
    u64 wr[32];
#pragma unroll
    for (int r = 0; r < 32; r++)
        wr[r] = *(const u64*)&Whh[(96 + r) * 512 + c2];

    for (int idx = tid; idx < SPB * 256; idx += 512) hdup[idx] = 0.f;
    for (int idx = tid; idx < SPB * 128; idx += 512) csm[idx] = 0.f;
    __syncthreads();

    // prefetch xz for t=0
    u64 xv0 = valid[0] ? *(const u64*)(xp[0]) : 0ull;
    u64 xv1 = valid[1] ? *(const u64*)(xp[1]) : 0ull;
    u64 xv2 = valid[2] ? *(const u64*)(xp[2]) : 0ull;

    for (int t = 0; t < nsteps; t++) {
        u64 acc0 = 0ull, acc1 = 0ull, acc2 = 0ull;
        const float* hb = hdup + i0 * 256;

        // rows 0..95 from SMEM weights
#pragma unroll 4
        for (int k = 0; k < 96; k += 2) {
            u64 w0 = *(const u64*)&ws[(size_t)k * 512 + c2];
            u64 w1 = *(const u64*)&ws[(size_t)(k + 1) * 512 + c2];
            ulonglong2 h0 = *(const ulonglong2*)(hb + 2 * k);
            ulonglong2 h1 = *(const ulonglong2*)(hb + 256 + 2 * k);
            fma2(acc0, h0.x, w0); fma2(acc0, h0.y, w1);
            fma2(acc1, h1.x, w0); fma2(acc1, h1.y, w1);
            if (ni == 3) {
                ulonglong2 h2 = *(const ulonglong2*)(hb + 512 + 2 * k);
                fma2(acc2, h2.x, w0); fma2(acc2, h2.y, w1);
            }
        }
        // rows 96..127 from register weights
#pragma unroll
        for (int r = 0; r < 32; r += 2) {
            ulonglong2 h0 = *(const ulonglong2*)(hb + 192 + 2 * r);
            ulonglong2 h1 = *(const ulonglong2*)(hb + 256 + 192 + 2 * r);
            fma2(acc0, h0.x, wr[r]); fma2(acc0, h0.y, wr[r + 1]);
            fma2(acc1, h1.x, wr[r]); fma2(acc1, h1.y, wr[r + 1]);
            if (ni == 3) {
                ulonglong2 h2 = *(const ulonglong2*)(hb + 512 + 192 + 2 * r);
                fma2(acc2, h2.x, wr[r]); fma2(acc2, h2.y, wr[r + 1]);
            }
        }

        *(u64*)&zsm[(i0 + 0) * 512 + c2] = add2(acc0, xv0);
        *(u64*)&zsm[(i0 + 1) * 512 + c2] = add2(acc1, xv1);
        if (ni == 3)
            *(u64*)&zsm[(i0 + 2) * 512 + c2] = add2(acc2, xv2);

        // prefetch xz for next step (clamped)
        int tn = (t + 1 < nsteps) ? (t + 1) : t;
        xv0 = valid[0] ? *(const u64*)(xp[0] + (long)tn * xstep) : 0ull;
        xv1 = valid[1] ? *(const u64*)(xp[1] + (long)tn * xstep) : 0ull;
        xv2 = valid[2] ? *(const u64*)(xp[2] + (long)tn * xstep) : 0ull;

        __syncthreads();

        // gates + state update (640 elems over 512 threads)
        for (int q = tid; q < SPB * 128; q += 512) {
            int i = q >> 7, hh = q & 127;
            const float* zrow = zsm + i * 512;
            float zi = zrow[hh];
            float zf = zrow[128 + hh];
            float zg = zrow[256 + hh];
            float zo = zrow[384 + hh];
            float cn = sigmf(zf) * csm[q] + sigmf(zi) * tanhfast(zg);
            float hv = sigmf(zo) * tanhfast(cn);
            csm[q] = cn;
            float2 hp; hp.x = hv; hp.y = hv;
            *(float2*)&hdup[i * 256 + 2 * hh] = hp;
            int s = seq0 + i;
            if (s < nseq) {
                long row = is_node ? ((long)(s >> 2) * 2048 + (s & 3))
                                   : ((long)(s >> 4) * 8192 + (s & 15));
                out[row * 128 + (long)t * ostep + hh] = hv;
            }
        }
        __syncthreads();
    }
}

// ---------------------------------------------------------------------------
// Final projection (unchanged)
// ---------------------------------------------------------------------------
__global__ __launch_bounds__(256) void final_k(
    const float* __restrict__ A, const float* __restrict__ W,
    const float* __restrict__ bias, float* __restrict__ out)
{
    __shared__ float ws[2048];
    __shared__ float as[32 * 264];
    const int tid = threadIdx.x;
    for (int i = tid; i < 2048; i += 256) ws[i] = W[i];

    long row0 = (long)blockIdx.x * 32;
    const float4* Ap = (const float4*)(A + row0 * 256);
    for (int i = tid; i < 2048; i += 256) {
        int r  = i >> 6;
        int c4 = i & 63;
        *(float4*)(as + r * 264 + c4 * 4) = Ap[(long)r * 64 + c4];
    }
    __syncthreads();

    int r = tid >> 3, c = tid & 7;
    float acc = bias[c];
    const float* arp = as + r * 264;
#pragma unroll 8
    for (int k = 0; k < 256; k++)
        acc += arp[k] * ws[k * 8 + c];
    out[(row0 + r) * 8 + c] = acc;
}

// ---------------------------------------------------------------------------
// Launch. Launch index 3 (the slot ncu empirically profiles) = 32-step LSTM
// diagnostic reading stale scratch (deterministic across replays) and
// writing into g_c1, which sgemm_c1 fully overwrites later.
// ---------------------------------------------------------------------------
extern "C" void kernel_launch(void* const* d_in, const int* in_sizes, int n_in,
                              void* d_out, int out_size)
{
    const float* x_seq = (const float*)d_in[0];
    const float* ea    = (const float*)d_in[1];
    const float* Wn1   = (const float*)d_in[2];
    const float* bn1   = (const float*)d_in[3];
    const float* Wn2   = (const float*)d_in[4];
    const float* bn2   = (const float*)d_in[5];
    const float* We1   = (const float*)d_in[6];
    const float* be1   = (const float*)d_in[7];
    const float* We2   = (const float*)d_in[8];
    const float* be2   = (const float*)d_in[9];
    const float* Wg1   = (const float*)d_in[10];
    const float* bg1   = (const float*)d_in[11];
    const float* Wg2   = (const float*)d_in[12];
    const float* bg2   = (const float*)d_in[13];
    const float* Wef1  = (const float*)d_in[14];
    const float* bef1  = (const float*)d_in[15];
    const float* Wef2  = (const float*)d_in[16];
    const float* bef2  = (const float*)d_in[17];
    const float* Wih_n = (const float*)d_in[18];
    const float* Whh_n = (const float*)d_in[19];
    const float* b_n   = (const float*)d_in[20];
    const float* Wih_e = (const float*)d_in[21];
    const float* Whh_e = (const float*)d_in[22];
    const float* b_e   = (const float*)d_in[23];
    const float* Wc1   = (const float*)d_in[24];
    const float* bc1   = (const float*)d_in[25];
    const float* Wc2   = (const float*)d_in[26];
    const float* bc2   = (const float*)d_in[27];
    float* out = (float*)d_out;

    (void)in_sizes; (void)n_in; (void)out_size;

    cudaFuncSetAttribute(lstm3,
                         cudaFuncAttributeMaxDynamicSharedMemorySize,
                         LSTM_SMEM_BYTES);

    float* nA = g_nA; float* nB = g_nB;
    float* eA = g_eA; float* eB = g_eB;

    dim3 gn1(1, 512);
    dim3 gn4(4, 512);
    dim3 ge1(1, 2048);
    dim3 ge4(4, 2048);

    // idx0-2: edge MLP layers 1-3
    sgemm_k8        <<<ge1, 256>>>(ea, We1, be1, eA, 262144, 128, 8);
    sgemm2<1, 1, 0> <<<ge1, 256>>>(eA, We2, be2, eB, 262144, 128, 128);
    sgemm2<1, 1, 0> <<<ge1, 256>>>(eB, Wef1, bef1, eA, 262144, 128, 128);
    // idx3: DIAGNOSTIC short LSTM (profiled slot). Stale scratch in, g_c1 out.
    lstm3<<<129, 512, LSTM_SMEM_BYTES>>>(g_xzn, Whh_n, g_c1 + 33554432,
                                         g_xze, Whh_e, g_c1, 32);
    // idx4: edge MLP layer 4  -> e4 in eB
    sgemm2<1, 1, 0> <<<ge1, 256>>>(eA, Wef2, bef2, eB, 262144, 128, 128);
    // idx5: edge LSTM input projection
    sgemm2<0, 1, 0> <<<ge4, 256>>>(eB, Wih_e, b_e, g_xze, 262144, 512, 128);
    // idx6-9: node path
    sgemm2<1, 1, 0> <<<gn1, 256>>>(x_seq, Wn1, bn1, nA, 65536, 128, 16);
    sgemm2<1, 1, 0> <<<gn1, 256>>>(nA, Wn2, bn2, nB, 65536, 128, 128);
    sgemm2<0, 1, 1> <<<gn1, 256>>>(nB, Wg1, bg1, nA, 65536, 128, 128);
    sgemm2<0, 1, 1> <<<gn1, 256>>>(nA, Wg2, bg2, nB, 65536, 128, 128);
    // idx10: node LSTM input projection
    sgemm2<0, 1, 0> <<<gn4, 256>>>(nB, Wih_n, b_n, g_xzn, 65536, 512, 128);
    // idx11: real fused LSTM -> hn in nA, he in eA
    lstm3<<<129, 512, LSTM_SMEM_BYTES>>>(g_xzn, Whh_n, nA,
                                         g_xze, Whh_e, eA, 512);
    // idx12-13: classifier
    sgemm_c1<<<dim3(2, 2048), 256>>>(nA, eA, Wc1, bc1, g_c1);
    final_k<<<8192, 256>>>(g_c1, Wc2, bc2, out);
}

// round 4
// speedup vs baseline: 1.4874x; 1.4874x over previous
#include <cuda_runtime.h>
#include <math.h>

// ---------------------------------------------------------------------------
// Problem: B=32,T=512,N=4,E=16, NI=16,EI=8, HN=HE=128, MH=256, C=8
// M_node=65536, M_edge=262144
// ---------------------------------------------------------------------------

typedef unsigned long long u64;

#define SPB 5
#define LSTM_SMEM_FLOATS (96*512 + SPB*256 + SPB*128 + SPB*512)
#define LSTM_SMEM_BYTES  (LSTM_SMEM_FLOATS * 4)

// ---- single aliased scratch arena: 240M floats = 960MB ----
// XZE [0,128M)  E4 [128M,160M)  H2/HE [160M,192M)  X2/HN [192M,200M)
// X4 [200M,208M)  XZN [208M,240M)
#define OFF_XZE 0L
#define OFF_E4  134217728L
#define OFF_H2  167772160L
#define OFF_X2  201326592L
#define OFF_X4  209715200L
#define OFF_XZN 218103808L
__device__ float g_arena[251658240];

// ---- packed fp32x2 helpers ----
__device__ __forceinline__ u64 pk2(float lo, float hi) {
    u64 r; asm("mov.b64 %0, {%1,%2};" : "=l"(r) : "f"(lo), "f"(hi)); return r;
}
__device__ __forceinline__ void up2(float& lo, float& hi, u64 v) {
    asm("mov.b64 {%0,%1}, %2;" : "=f"(lo), "=f"(hi) : "l"(v));
}
__device__ __forceinline__ void fma2(u64& c, u64 a, u64 b) {
    asm("fma.rn.f32x2 %0, %1, %2, %0;" : "+l"(c) : "l"(a), "l"(b));
}
__device__ __forceinline__ u64 add2(u64 a, u64 b) {
    u64 r; asm("add.rn.f32x2 %0, %1, %2;" : "=l"(r) : "l"(a), "l"(b)); return r;
}

__device__ __forceinline__ float sigmf(float x) { return 1.0f / (1.0f + __expf(-x)); }
__device__ __forceinline__ float tanhfast(float x) { return 1.0f - 2.0f / (__expf(2.0f * x) + 1.0f); }

// 8x8 microtile GEMM from SMEM-resident transposed activations + weights.
// at: activations transposed, at[k*132 + r] (132 stride: f4-aligned, low conflict)
// w:  weights w[k*128 + c]
__device__ __forceinline__ void smem_gemm(
    const float* at, const float* w, int K, int tx, int ty, u64 acc[4][8])
{
#pragma unroll
    for (int i = 0; i < 4; i++)
#pragma unroll
        for (int j = 0; j < 8; j++) acc[i][j] = 0ull;
#pragma unroll 8
    for (int k = 0; k < K; k++) {
        ulonglong2 aa = *(const ulonglong2*)&at[k * 132 + ty];
        ulonglong2 ab = *(const ulonglong2*)&at[k * 132 + ty + 4];
        float4 c0 = *(const float4*)&w[k * 128 + tx];
        float4 c1 = *(const float4*)&w[k * 128 + tx + 4];
        u64 bd[8];
        bd[0] = pk2(c0.x, c0.x); bd[1] = pk2(c0.y, c0.y);
        bd[2] = pk2(c0.z, c0.z); bd[3] = pk2(c0.w, c0.w);
        bd[4] = pk2(c1.x, c1.x); bd[5] = pk2(c1.y, c1.y);
        bd[6] = pk2(c1.z, c1.z); bd[7] = pk2(c1.w, c1.w);
        u64 ap[4] = { aa.x, aa.y, ab.x, ab.y };
#pragma unroll
        for (int i = 0; i < 4; i++)
#pragma unroll
            for (int j = 0; j < 8; j++)
                fma2(acc[i][j], ap[i], bd[j]);
    }
}

// unpack acc -> v[8][8] then apply bias(+mix)+relu
__device__ __forceinline__ void unpack_epi(
    u64 acc[4][8], const float* bias, int tx, int MIX, float v[8][8])
{
#pragma unroll
    for (int i = 0; i < 4; i++)
#pragma unroll
        for (int j = 0; j < 8; j++)
            up2(v[2 * i][j], v[2 * i + 1][j], acc[i][j]);
    float bv[8];
    *(float4*)&bv[0] = *(const float4*)&bias[tx];
    *(float4*)&bv[4] = *(const float4*)&bias[tx + 4];
    if (MIX) {
#pragma unroll
        for (int g = 0; g < 2; g++) {
            float s[8];
#pragma unroll
            for (int j = 0; j < 8; j++)
                s[j] = v[4*g][j] + v[4*g+1][j] + v[4*g+2][j] + v[4*g+3][j];
#pragma unroll
            for (int r = 0; r < 4; r++)
#pragma unroll
                for (int j = 0; j < 8; j++)
                    v[4*g+r][j] = fmaxf((s[j] + v[4*g+r][j]) * 0.2f + bv[j], 0.f);
        }
    } else {
#pragma unroll
        for (int r = 0; r < 8; r++)
#pragma unroll
            for (int j = 0; j < 8; j++)
                v[r][j] = fmaxf(v[r][j] + bv[j], 0.f);
    }
}

// ---------------------------------------------------------------------------
// Fused two-layer MLP block kernel. 128-row tile, layer widths K1->128->128.
// MIX: apply graph-conv mixing (node path) on both layer epilogues.
// SMEM: w1[K1*128] + w2[128*128] + at[128*132]  (<= 198.7KB for K1=128)
// ---------------------------------------------------------------------------
template <int K1, int MIX>
__global__ __launch_bounds__(256) void fused2(
    const float* __restrict__ in,  const float* __restrict__ W1,
    const float* __restrict__ b1,  const float* __restrict__ W2,
    const float* __restrict__ b2,  float* __restrict__ out)
{
    extern __shared__ float s[];
    float* w1 = s;                    // K1*128
    float* w2 = w1 + K1 * 128;        // 128*128
    float* at = w2 + 128 * 128;       // 128*132
    const int tid = threadIdx.x;
    const long bm = (long)blockIdx.x * 128;
    const int tx = (tid & 15) * 8;
    const int ty = (tid >> 4) * 8;

    for (int i = tid; i < (K1 * 128) / 4; i += 256)
        ((float4*)w1)[i] = ((const float4*)W1)[i];
    for (int i = tid; i < (128 * 128) / 4; i += 256)
        ((float4*)w2)[i] = ((const float4*)W2)[i];

    // stage input transposed: at[k][r]
    {
        const int r = tid >> 1;
        const int h = tid & 1;
        const int C = K1 / 2;
        const float* p = in + (bm + r) * K1 + h * C;
#pragma unroll
        for (int c = 0; c < C; c += 4) {
            float4 vv = *(const float4*)(p + c);
            at[(h * C + c + 0) * 132 + r] = vv.x;
            at[(h * C + c + 1) * 132 + r] = vv.y;
            at[(h * C + c + 2) * 132 + r] = vv.z;
            at[(h * C + c + 3) * 132 + r] = vv.w;
        }
    }
    __syncthreads();

    u64 acc[4][8];
    float v[8][8];

    // layer 1
    smem_gemm(at, w1, K1, tx, ty, acc);
    __syncthreads();                       // all at reads complete
    unpack_epi(acc, b1, tx, MIX, v);
    // store transposed for layer 2
#pragma unroll
    for (int j = 0; j < 8; j++) {
        float* q = at + (tx + j) * 132 + ty;
        *(float4*)(q)     = make_float4(v[0][j], v[1][j], v[2][j], v[3][j]);
        *(float4*)(q + 4) = make_float4(v[4][j], v[5][j], v[6][j], v[7][j]);
    }
    __syncthreads();

    // layer 2
    smem_gemm(at, w2, 128, tx, ty, acc);
    unpack_epi(acc, b2, tx, MIX, v);
#pragma unroll
    for (int r = 0; r < 8; r++) {
        float* q = out + (bm + ty + r) * 128 + tx;
        *(float4*)(q)     = make_float4(v[r][0], v[r][1], v[r][2], v[r][3]);
        *(float4*)(q + 4) = make_float4(v[r][4], v[r][5], v[r][6], v[r][7]);
    }
}

// ---------------------------------------------------------------------------
// f32x2 SGEMM (for the two Wih input-projection GEMMs). Unchanged.
// ---------------------------------------------------------------------------
__global__ __launch_bounds__(256) void sgemm2(
    const float* __restrict__ A, const float* __restrict__ B,
    const float* __restrict__ bias, float* __restrict__ C,
    int M, int N, int K)
{
    __shared__ float As[16][128];
    __shared__ float Bs[16][128];
    const int tid  = threadIdx.x;
    const int bm   = blockIdx.y * 128;
    const int bn   = blockIdx.x * 128;
    const int arow = tid >> 1;
    const int acol = (tid & 1) * 8;
    const int brow = tid >> 4;
    const int bcol = (tid & 15) * 8;
    const int tx   = (tid & 15) * 8;
    const int ty   = (tid >> 4) * 8;

    const float* Ap = A + (size_t)(bm + arow) * K + acol;
    const float* Bp = B + (size_t)brow * N + bn + bcol;

    float4 a0 = *(const float4*)(Ap);
    float4 a1 = *(const float4*)(Ap + 4);
    float4 b0 = *(const float4*)(Bp);
    float4 b1 = *(const float4*)(Bp + 4);

    u64 acc[4][8];
#pragma unroll
    for (int i = 0; i < 4; i++)
#pragma unroll
        for (int j = 0; j < 8; j++) acc[i][j] = 0ull;

    int k0 = 0;
    for (;;) {
        As[acol + 0][arow] = a0.x; As[acol + 1][arow] = a0.y;
        As[acol + 2][arow] = a0.z; As[acol + 3][arow] = a0.w;
        As[acol + 4][arow] = a1.x; As[acol + 5][arow] = a1.y;
        As[acol + 6][arow] = a1.z; As[acol + 7][arow] = a1.w;
        *(float4*)&Bs[brow][bcol]     = b0;
        *(float4*)&Bs[brow][bcol + 4] = b1;
        __syncthreads();

        k0 += 16;
        bool more = (k0 < K);
        if (more) {
            a0 = *(const float4*)(Ap + k0);
            a1 = *(const float4*)(Ap + k0 + 4);
            b0 = *(const float4*)(Bp + (size_t)k0 * N);
            b1 = *(const float4*)(Bp + (size_t)k0 * N + 4);
        }

#pragma unroll
        for (int kk = 0; kk < 16; kk++) {
            ulonglong2 apA = *(const ulonglong2*)&As[kk][ty];
            ulonglong2 apB = *(const ulonglong2*)&As[kk][ty + 4];
            float4 c0 = *(const float4*)&Bs[kk][tx];
            float4 c1 = *(const float4*)&Bs[kk][tx + 4];
            u64 bd[8];
            bd[0] = pk2(c0.x, c0.x); bd[1] = pk2(c0.y, c0.y);
            bd[2] = pk2(c0.z, c0.z); bd[3] = pk2(c0.w, c0.w);
            bd[4] = pk2(c1.x, c1.x); bd[5] = pk2(c1.y, c1.y);
            bd[6] = pk2(c1.z, c1.z); bd[7] = pk2(c1.w, c1.w);
            u64 ap[4] = { apA.x, apA.y, apB.x, apB.y };
#pragma unroll
            for (int i = 0; i < 4; i++)
#pragma unroll
                for (int j = 0; j < 8; j++)
                    fma2(acc[i][j], ap[i], bd[j]);
        }
        if (!more) break;
        __syncthreads();
    }

    float v[8][8];
#pragma unroll
    for (int i = 0; i < 4; i++)
#pragma unroll
        for (int j = 0; j < 8; j++)
            up2(v[2 * i][j], v[2 * i + 1][j], acc[i][j]);

    float bv[8];
    *(float4*)&bv[0] = *(const float4*)&bias[bn + tx];
    *(float4*)&bv[4] = *(const float4*)&bias[bn + tx + 4];
#pragma unroll
    for (int r = 0; r < 8; r++) {
        float* Crow = C + (size_t)(bm + ty + r) * N + bn + tx;
        *(float4*)(Crow)     = make_float4(v[r][0]+bv[0], v[r][1]+bv[1], v[r][2]+bv[2], v[r][3]+bv[3]);
        *(float4*)(Crow + 4) = make_float4(v[r][4]+bv[4], v[r][5]+bv[5], v[r][6]+bv[6], v[r][7]+bv[7]);
    }
}

// ---------------------------------------------------------------------------
// Classifier fused: gather(src,dst,he) @ Wc1 + bc1 -> relu -> @ Wc2 + bc2.
// BM=64, BN=256 (full MH), K=384 gathered. Then 256->8 reduction in SMEM.
// ---------------------------------------------------------------------------
__global__ __launch_bounds__(256) void c1final(
    const float* __restrict__ hn, const float* __restrict__ he,
    const float* __restrict__ Wc1, const float* __restrict__ bc1,
    const float* __restrict__ Wc2, const float* __restrict__ bc2,
    float* __restrict__ out)
{
    extern __shared__ float s[];
    float* As  = s;              // 16 * 68
    float* Bs  = As + 16 * 68;   // 16 * 256
    float* ct  = Bs + 16 * 256;  // 256 * 68  (ct[k*68 + r])
    float* wc2 = ct + 256 * 68;  // 256 * 8
    const int tid = threadIdx.x;
    const long bm = (long)blockIdx.x * 64;
    const int tx = (tid & 31) * 8;   // 0..248
    const int ty = (tid >> 5) * 8;   // 0..56

    for (int i = tid; i < 512; i += 256)
        ((float4*)wc2)[i] = ((const float4*)Wc2)[i];

    // gather pointers for A staging (each thread: row arow, 4 cols)
    const int arow = tid >> 2;
    const int acol = (tid & 3) * 4;
    const long row = bm + arow;
    const long bt  = row >> 4;
    const int  e   = (int)(row & 15);
    const float* seg0 = hn + (bt * 4 + (e >> 2)) * 128;
    const float* seg1 = hn + (bt * 4 + (e & 3)) * 128;
    const float* seg2 = he + row * 128;

    const int brow = tid >> 4;            // 0..15
    const int bcol = (tid & 15) * 16;     // 16 floats each

    u64 acc[4][8];
#pragma unroll
    for (int i = 0; i < 4; i++)
#pragma unroll
        for (int j = 0; j < 8; j++) acc[i][j] = 0ull;

    for (int k0 = 0; k0 < 384; k0 += 16) {
        const float* sp = (k0 < 128) ? seg0 : ((k0 < 256) ? seg1 : seg2);
        float4 av = *(const float4*)(sp + (k0 & 127) + acol);
        const float* bp = Wc1 + (size_t)(k0 + brow) * 256 + bcol;
        float4 bv0 = *(const float4*)(bp);
        float4 bv1 = *(const float4*)(bp + 4);
        float4 bv2 = *(const float4*)(bp + 8);
        float4 bv3 = *(const float4*)(bp + 12);
        As[(acol + 0) * 68 + arow] = av.x;
        As[(acol + 1) * 68 + arow] = av.y;
        As[(acol + 2) * 68 + arow] = av.z;
        As[(acol + 3) * 68 + arow] = av.w;
        float* bq = Bs + brow * 256 + bcol;
        *(float4*)(bq)      = bv0;
        *(float4*)(bq + 4)  = bv1;
        *(float4*)(bq + 8)  = bv2;
        *(float4*)(bq + 12) = bv3;
        __syncthreads();

#pragma unroll
        for (int kk = 0; kk < 16; kk++) {
            ulonglong2 aa = *(const ulonglong2*)&As[kk * 68 + ty];
            ulonglong2 ab = *(const ulonglong2*)&As[kk * 68 + ty + 4];
            float4 c0 = *(const float4*)&Bs[kk * 256 + tx];
            float4 c1 = *(const float4*)&Bs[kk * 256 + tx + 4];
            u64 bd[8];
            bd[0] = pk2(c0.x, c0.x); bd[1] = pk2(c0.y, c0.y);
            bd[2] = pk2(c0.z, c0.z); bd[3] = pk2(c0.w, c0.w);
            bd[4] = pk2(c1.x, c1.x); bd[5] = pk2(c1.y, c1.y);
            bd[6] = pk2(c1.z, c1.z); bd[7] = pk2(c1.w, c1.w);
            u64 ap[4] = { aa.x, aa.y, ab.x, ab.y };
#pragma unroll
            for (int i = 0; i < 4; i++)
#pragma unroll
                for (int j = 0; j < 8; j++)
                    fma2(acc[i][j], ap[i], bd[j]);
        }
        __syncthreads();
    }

    // epilogue: relu(c1+bc1) -> ct transposed
    float v[8][8];
#pragma unroll
    for (int i = 0; i < 4; i++)
#pragma unroll
        for (int j = 0; j < 8; j++)
            up2(v[2 * i][j], v[2 * i + 1][j], acc[i][j]);
    float bv[8];
    *(float4*)&bv[0] = *(const float4*)&bc1[tx];
    *(float4*)&bv[4] = *(const float4*)&bc1[tx + 4];
#pragma unroll
    for (int j = 0; j < 8; j++) {
        float* q = ct + (tx + j) * 68 + ty;
        *(float4*)(q)     = make_float4(fmaxf(v[0][j]+bv[j],0.f), fmaxf(v[1][j]+bv[j],0.f),
                                        fmaxf(v[2][j]+bv[j],0.f), fmaxf(v[3][j]+bv[j],0.f));
        *(float4*)(q + 4) = make_float4(fmaxf(v[4][j]+bv[j],0.f), fmaxf(v[5][j]+bv[j],0.f),
                                        fmaxf(v[6][j]+bv[j],0.f), fmaxf(v[7][j]+bv[j],0.f));
    }
    __syncthreads();

    // final 256->8: each thread 1 row x 2 cols
    {
        const int r = tid >> 2;
        const int c = (tid & 3) * 2;
        float f0 = bc2[c], f1 = bc2[c + 1];
#pragma unroll 8
        for (int k = 0; k < 256; k++) {
            float a = ct[k * 68 + r];
            f0 += a * wc2[k * 8 + c];
            f1 += a * wc2[k * 8 + c + 1];
        }
        float* q = out + (bm + r) * 8 + c;
        q[0] = f0; q[1] = f1;
    }
}

// ---------------------------------------------------------------------------
// LSTM (unchanged from round 3, 512 threads, f32x2)
// ---------------------------------------------------------------------------
__global__ __launch_bounds__(512, 1) void lstm3(
    const float* __restrict__ xz_n, const float* __restrict__ Whh_n, float* __restrict__ hn,
    const float* __restrict__ xz_e, const float* __restrict__ Whh_e, float* __restrict__ he,
    int nsteps)
{
    extern __shared__ float sm[];
    float* ws   = sm;
    float* hdup = ws + 96 * 512;
    float* csm  = hdup + SPB * 256;
    float* zsm  = csm + SPB * 128;

    const int tid = threadIdx.x;
    const int sub = tid >> 8;
    const int lt  = tid & 255;
    const int c2  = 2 * lt;
    const int i0  = sub ? 3 : 0;
    const int ni  = sub ? 2 : 3;

    const float* Whh;
    const float* xz;
    float* out;
    int seq0, nseq;
    int is_node;

    if (blockIdx.x < 26) {
        Whh = Whh_n; xz = xz_n; out = hn;
        seq0 = blockIdx.x * SPB; nseq = 128; is_node = 1;
    } else {
        Whh = Whh_e; xz = xz_e; out = he;
        seq0 = (blockIdx.x - 26) * SPB; nseq = 512; is_node = 0;
    }
    const long xstep = is_node ? (4 * 512) : (16 * 512);
    const long ostep = is_node ? (4 * 128) : (16 * 128);

    const float* xp[3];
    int valid[3];
#pragma unroll
    for (int j = 0; j < 3; j++) {
        int sq = seq0 + i0 + j;
        valid[j] = (j < ni) && (sq < nseq);
        long row = is_node ? ((long)(sq >> 2) * 2048 + (sq & 3))
                           : ((long)(sq >> 4) * 8192 + (sq & 15));
        xp[j] = xz + row * 512 + c2;
    }

    for (int idx = tid; idx < (96 * 512) / 4; idx += 512)
        ((float4*)ws)[idx] = ((const float4*)Whh)[idx];
    u64 wr[32];
#pragma unroll
    for (int r = 0; r < 32; r++)
        wr[r] = *(const u64*)&Whh[(96 + r) * 512 + c2];

    for (int idx = tid; idx < SPB * 256; idx += 512) hdup[idx] = 0.f;
    for (int idx = tid; idx < SPB * 128; idx += 512) csm[idx] = 0.f;
    __syncthreads();

    u64 xv0 = valid[0] ? *(const u64*)(xp[0]) : 0ull;
    u64 xv1 = valid[1] ? *(const u64*)(xp[1]) : 0ull;
    u64 xv2 = valid[2] ? *(const u64*)(xp[2]) : 0ull;

    for (int t = 0; t < nsteps; t++) {
        u64 acc0 = 0ull, acc1 = 0ull, acc2 = 0ull;
        const float* hb = hdup + i0 * 256;

#pragma unroll 4
        for (int k = 0; k < 96; k += 2) {
            u64 w0 = *(const u64*)&ws[(size_t)k * 512 + c2];
            u64 w1 = *(const u64*)&ws[(size_t)(k + 1) * 512 + c2];
            ulonglong2 h0 = *(const ulonglong2*)(hb + 2 * k);
            ulonglong2 h1 = *(const ulonglong2*)(hb + 256 + 2 * k);
            fma2(acc0, h0.x, w0); fma2(acc0, h0.y, w1);
            fma2(acc1, h1.x, w0); fma2(acc1, h1.y, w1);
            if (ni == 3) {
                ulonglong2 h2 = *(const ulonglong2*)(hb + 512 + 2 * k);
                fma2(acc2, h2.x, w0); fma2(acc2, h2.y, w1);
            }
        }
#pragma unroll
        for (int r = 0; r < 32; r += 2) {
            ulonglong2 h0 = *(const ulonglong2*)(hb + 192 + 2 * r);
            ulonglong2 h1 = *(const ulonglong2*)(hb + 256 + 192 + 2 * r);
            fma2(acc0, h0.x, wr[r]); fma2(acc0, h0.y, wr[r + 1]);
            fma2(acc1, h1.x, wr[r]); fma2(acc1, h1.y, wr[r + 1]);
            if (ni == 3) {
                ulonglong2 h2 = *(const ulonglong2*)(hb + 512 + 192 + 2 * r);
                fma2(acc2, h2.x, wr[r]); fma2(acc2, h2.y, wr[r + 1]);
            }
        }

        *(u64*)&zsm[(i0 + 0) * 512 + c2] = add2(acc0, xv0);
        *(u64*)&zsm[(i0 + 1) * 512 + c2] = add2(acc1, xv1);
        if (ni == 3)
            *(u64*)&zsm[(i0 + 2) * 512 + c2] = add2(acc2, xv2);

        int tn = (t + 1 < nsteps) ? (t + 1) : t;
        xv0 = valid[0] ? *(const u64*)(xp[0] + (long)tn * xstep) : 0ull;
        xv1 = valid[1] ? *(const u64*)(xp[1] + (long)tn * xstep) : 0ull;
        xv2 = valid[2] ? *(const u64*)(xp[2] + (long)tn * xstep) : 0ull;

        __syncthreads();

        for (int q = tid; q < SPB * 128; q += 512) {
            int i = q >> 7, hh = q & 127;
            const float* zrow = zsm + i * 512;
            float zi = zrow[hh];
            float zf = zrow[128 + hh];
            float zg = zrow[256 + hh];
            float zo = zrow[384 + hh];
            float cn = sigmf(zf) * csm[q] + sigmf(zi) * tanhfast(zg);
            float hv = sigmf(zo) * tanhfast(cn);
            csm[q] = cn;
            float2 hp; hp.x = hv; hp.y = hv;
            *(float2*)&hdup[i * 256 + 2 * hh] = hp;
            int sq = seq0 + i;
            if (sq < nseq) {
                long row = is_node ? ((long)(sq >> 2) * 2048 + (sq & 3))
                                   : ((long)(sq >> 4) * 8192 + (sq & 15));
                out[row * 128 + (long)t * ostep + hh] = hv;
            }
        }
        __syncthreads();
    }
}

// ---------------------------------------------------------------------------
// Diagnostic: pure 32MB static->static copy (profiled slot idx3).
// Measures achievable bandwidth on the scratch arena. Dest overwritten later.
// ---------------------------------------------------------------------------
__global__ void copy_diag(const float4* __restrict__ src, float4* __restrict__ dst)
{
    long base = (long)blockIdx.x * 1024 + threadIdx.x;
#pragma unroll
    for (int i = 0; i < 4; i++)
        dst[base + i * 256] = src[base + i * 256];
}

// ---------------------------------------------------------------------------
// Launch
// ---------------------------------------------------------------------------
extern "C" void kernel_launch(void* const* d_in, const int* in_sizes, int n_in,
                              void* d_out, int out_size)
{
    const float* x_seq = (const float*)d_in[0];
    const float* ea    = (const float*)d_in[1];
    const float* Wn1   = (const float*)d_in[2];
    const float* bn1   = (const float*)d_in[3];
    const float* Wn2   = (const float*)d_in[4];
    const float* bn2   = (const float*)d_in[5];
    const float* We1   = (const float*)d_in[6];
    const float* be1   = (const float*)d_in[7];
    const float* We2   = (const float*)d_in[8];
    const float* be2   = (const float*)d_in[9];
    const float* Wg1   = (const float*)d_in[10];
    const float* bg1   = (const float*)d_in[11];
    const float* Wg2   = (const float*)d_in[12];
    const float* bg2   = (const float*)d_in[13];
    const float* Wef1  = (const float*)d_in[14];
    const float* bef1  = (const float*)d_in[15];
    const float* Wef2  = (const float*)d_in[16];
    const float* bef2  = (const float*)d_in[17];
    const float* Wih_n = (const float*)d_in[18];
    const float* Whh_n = (const float*)d_in[19];
    const float* b_n   = (const float*)d_in[20];
    const float* Wih_e = (const float*)d_in[21];
    const float* Whh_e = (const float*)d_in[22];
    const float* b_e   = (const float*)d_in[23];
    const float* Wc1   = (const float*)d_in[24];
    const float* bc1   = (const float*)d_in[25];
    const float* Wc2   = (const float*)d_in[26];
    const float* bc2   = (const float*)d_in[27];
    float* out = (float*)d_out;

    (void)in_sizes; (void)n_in; (void)out_size;

    // dynamic smem limits
    const int SM_F2_8   = (8*128 + 128*128 + 128*132) * 4;
    const int SM_F2_16  = (16*128 + 128*128 + 128*132) * 4;
    const int SM_F2_128 = (128*128 + 128*128 + 128*132) * 4;
    const int SM_C1F    = (16*68 + 16*256 + 256*68 + 256*8) * 4;
    cudaFuncSetAttribute(fused2<8,0>,   cudaFuncAttributeMaxDynamicSharedMemorySize, SM_F2_8);
    cudaFuncSetAttribute(fused2<128,0>, cudaFuncAttributeMaxDynamicSharedMemorySize, SM_F2_128);
    cudaFuncSetAttribute(fused2<16,0>,  cudaFuncAttributeMaxDynamicSharedMemorySize, SM_F2_16);
    cudaFuncSetAttribute(fused2<128,1>, cudaFuncAttributeMaxDynamicSharedMemorySize, SM_F2_128);
    cudaFuncSetAttribute(c1final,       cudaFuncAttributeMaxDynamicSharedMemorySize, SM_C1F);
    cudaFuncSetAttribute(lstm3,         cudaFuncAttributeMaxDynamicSharedMemorySize, LSTM_SMEM_BYTES);

    float* AR = g_arena;
    float* xze = AR + OFF_XZE;
    float* e4  = AR + OFF_E4;
    float* h2  = AR + OFF_H2;    // later: he
    float* x2  = AR + OFF_X2;    // later: hn
    float* x4  = AR + OFF_X4;
    float* xzn = AR + OFF_XZN;

    // idx0: edge layers 1+2  (ea -> h2)
    fused2<8,0><<<2048, 256, SM_F2_8>>>(ea, We1, be1, We2, be2, h2);
    // idx1: edge layers 3+4  (h2 -> e4)
    fused2<128,0><<<2048, 256, SM_F2_128>>>(h2, Wef1, bef1, Wef2, bef2, e4);
    // idx2: node layers 1+2  (x_seq -> x2)
    fused2<16,0><<<512, 256, SM_F2_16>>>(x_seq, Wn1, bn1, Wn2, bn2, x2);
    // idx3: DIAGNOSTIC 32MB arena copy (profiled slot; dest overwritten at idx5)
    copy_diag<<<2048, 256>>>((const float4*)e4, (float4*)xze);
    // idx4: node graph-conv layers (x2 -> x4, mixes fused)
    fused2<128,1><<<512, 256, SM_F2_128>>>(x2, Wg1, bg1, Wg2, bg2, x4);
    // idx5: edge LSTM input projection (e4 -> xze)
    sgemm2<<<dim3(4, 2048), 256>>>(e4, Wih_e, b_e, xze, 262144, 512, 128);
    // idx6: node LSTM input projection (x4 -> xzn)
    sgemm2<<<dim3(4, 512), 256>>>(x4, Wih_n, b_n, xzn, 65536, 512, 128);
    // idx7: fused LSTM -> hn (x2 region), he (h2 region)
    lstm3<<<129, 512, LSTM_SMEM_BYTES>>>(xzn, Whh_n, x2, xze, Whh_e, h2, 512);
    // idx8: classifier fused (gather + Wc1 + relu + Wc2) -> out
    c1final<<<4096, 256, SM_C1F>>>(x2, h2, Wc1, bc1, Wc2, bc2, out);
}

// round 5
// speedup vs baseline: 5.2481x; 3.5283x over previous
#include <cuda_runtime.h>
#include <cuda_fp16.h>
#include <math.h>

// ---------------------------------------------------------------------------
// Problem: B=32,T=512,N=4,E=16, NI=16,EI=8, HN=HE=128, MH=256, C=8
// M_node=65536, M_edge=262144
// Key HW fact (measured r4): __device__ statics are host-resident via
// NVLink-C2C (~200-234 GB/s, L2-bypassed). Minimize static traffic.
// ---------------------------------------------------------------------------

typedef unsigned long long u64;

#define SPB 5
#define LSTM_SMEM_FLOATS (96*512 + SPB*256 + SPB*128 + SPB*512)
#define LSTM_SMEM_BYTES  (LSTM_SMEM_FLOATS * 4)

// ---- scratch arena (host-resident; keep small): 480MB ----
// xze_h: 262144*512 half = 67108864 floats-equiv
// xzn_h: 65536*512 half  = 16777216
// hn:    65536*128 f32   = 8388608
// he:    262144*128 f32  = 33554432
#define OFF_XZE_H 0L
#define OFF_XZN_H 67108864L
#define OFF_HN    83886080L
#define OFF_HE    92274688L
__device__ float g_arena[125829120];

// ---- packed fp32x2 helpers ----
__device__ __forceinline__ u64 pk2(float lo, float hi) {
    u64 r; asm("mov.b64 %0, {%1,%2};" : "=l"(r) : "f"(lo), "f"(hi)); return r;
}
__device__ __forceinline__ void up2(float& lo, float& hi, u64 v) {
    asm("mov.b64 {%0,%1}, %2;" : "=f"(lo), "=f"(hi) : "l"(v));
}
__device__ __forceinline__ void fma2(u64& c, u64 a, u64 b) {
    asm("fma.rn.f32x2 %0, %1, %2, %0;" : "+l"(c) : "l"(a), "l"(b));
}
__device__ __forceinline__ u64 add2(u64 a, u64 b) {
    u64 r; asm("add.rn.f32x2 %0, %1, %2;" : "=l"(r) : "l"(a), "l"(b)); return r;
}

// ---- MUFU-free exp (FMA pipe only). Valid for |x| <= ~40, err ~1e-7 ----
__device__ __forceinline__ float pexp(float x) {
    float t = x * 1.44269504088896f;
    float k = t + 12582912.0f;                    // RNE integer in mantissa
    int   e = __float_as_int(k) - 0x4B400000;     // bits(12582912.f)
    float n = k - 12582912.0f;
    float f = t - n;                              // f in [-0.5, 0.5]
    float p =              1.54035304e-4f;
    p = fmaf(p, f, 1.33335581e-3f);
    p = fmaf(p, f, 9.61812911e-3f);
    p = fmaf(p, f, 5.55041087e-2f);
    p = fmaf(p, f, 2.40226507e-1f);
    p = fmaf(p, f, 6.93147181e-1f);
    p = fmaf(p, f, 1.0f);
    float s = __int_as_float((e + 127) << 23);
    return p * s;
}
__device__ __forceinline__ float rcpa(float x) {
    float r; asm("rcp.approx.f32 %0, %1;" : "=f"(r) : "f"(x)); return r;
}
__device__ __forceinline__ float clamp15(float x) {
    return fminf(fmaxf(x, -15.f), 15.f);
}

// ---------------------------------------------------------------------------
// SMEM microtile GEMM: at[k*132+r] (transposed activations), w[k*128+c]
// ---------------------------------------------------------------------------
__device__ __forceinline__ void smem_gemm(
    const float* at, const float* w, int K, int tx, int ty, u64 acc[4][8])
{
#pragma unroll
    for (int i = 0; i < 4; i++)
#pragma unroll
        for (int j = 0; j < 8; j++) acc[i][j] = 0ull;
#pragma unroll 8
    for (int k = 0; k < K; k++) {
        ulonglong2 aa = *(const ulonglong2*)&at[k * 132 + ty];
        ulonglong2 ab = *(const ulonglong2*)&at[k * 132 + ty + 4];
        float4 c0 = *(const float4*)&w[k * 128 + tx];
        float4 c1 = *(const float4*)&w[k * 128 + tx + 4];
        u64 bd[8];
        bd[0] = pk2(c0.x, c0.x); bd[1] = pk2(c0.y, c0.y);
        bd[2] = pk2(c0.z, c0.z); bd[3] = pk2(c0.w, c0.w);
        bd[4] = pk2(c1.x, c1.x); bd[5] = pk2(c1.y, c1.y);
        bd[6] = pk2(c1.z, c1.z); bd[7] = pk2(c1.w, c1.w);
        u64 ap[4] = { aa.x, aa.y, ab.x, ab.y };
#pragma unroll
        for (int i = 0; i < 4; i++)
#pragma unroll
            for (int j = 0; j < 8; j++)
                fma2(acc[i][j], ap[i], bd[j]);
    }
}

__device__ __forceinline__ void unpack_epi(
    u64 acc[4][8], const float* bias, int tx, int MIX, float v[8][8])
{
#pragma unroll
    for (int i = 0; i < 4; i++)
#pragma unroll
        for (int j = 0; j < 8; j++)
            up2(v[2 * i][j], v[2 * i + 1][j], acc[i][j]);
    float bv[8];
    *(float4*)&bv[0] = *(const float4*)&bias[tx];
    *(float4*)&bv[4] = *(const float4*)&bias[tx + 4];
    if (MIX) {
#pragma unroll
        for (int g = 0; g < 2; g++) {
            float s[8];
#pragma unroll
            for (int j = 0; j < 8; j++)
                s[j] = v[4*g][j] + v[4*g+1][j] + v[4*g+2][j] + v[4*g+3][j];
#pragma unroll
            for (int r = 0; r < 4; r++)
#pragma unroll
                for (int j = 0; j < 8; j++)
                    v[4*g+r][j] = fmaxf((s[j] + v[4*g+r][j]) * 0.2f + bv[j], 0.f);
        }
    } else {
#pragma unroll
        for (int r = 0; r < 8; r++)
#pragma unroll
            for (int j = 0; j < 8; j++)
                v[r][j] = fmaxf(v[r][j] + bv[j], 0.f);
    }
}

__device__ __forceinline__ void store_at_T(float* at, float v[8][8], int tx, int ty)
{
#pragma unroll
    for (int j = 0; j < 8; j++) {
        float* q = at + (tx + j) * 132 + ty;
        *(float4*)(q)     = make_float4(v[0][j], v[1][j], v[2][j], v[3][j]);
        *(float4*)(q + 4) = make_float4(v[4][j], v[5][j], v[6][j], v[7][j]);
    }
}

// ---------------------------------------------------------------------------
// Whole path in ONE kernel: in -> L1..L4 (relu; MIX34 -> graph-conv mix on
// layers 3,4) -> Wih projection (512 wide) -> xz as fp16.
// No intermediates ever leave the SM.  SMEM: wa 64KB + wb 64KB + at 66KB.
// ---------------------------------------------------------------------------
template <int K1, int MIX34>
__global__ __launch_bounds__(256) void fused_all(
    const float* __restrict__ in,
    const float* __restrict__ W1, const float* __restrict__ b1,
    const float* __restrict__ W2, const float* __restrict__ b2,
    const float* __restrict__ W3, const float* __restrict__ b3,
    const float* __restrict__ W4, const float* __restrict__ b4,
    const float* __restrict__ Wih, const float* __restrict__ bih,
    __half* __restrict__ xz)
{
    extern __shared__ float s[];
    float* wa = s;                 // 128*128
    float* wb = wa + 128 * 128;    // 128*128
    float* at = wb + 128 * 128;    // 128*132
    const int tid = threadIdx.x;
    const long bm = (long)blockIdx.x * 128;
    const int tx = (tid & 15) * 8;
    const int ty = (tid >> 4) * 8;

    // load W1 (K1x128) + W2, stage input transposed
    for (int i = tid; i < K1 * 32; i += 256)
        ((float4*)wa)[i] = ((const float4*)W1)[i];
    for (int i = tid; i < 4096; i += 256)
        ((float4*)wb)[i] = ((const float4*)W2)[i];
    {
        const int r = tid >> 1;
        const int h = tid & 1;
        const int C = K1 / 2;
        const float* p = in + (bm + r) * K1 + h * C;
#pragma unroll
        for (int c = 0; c < C; c += 4) {
            float4 vv = *(const float4*)(p + c);
            at[(h * C + c + 0) * 132 + r] = vv.x;
            at[(h * C + c + 1) * 132 + r] = vv.y;
            at[(h * C + c + 2) * 132 + r] = vv.z;
            at[(h * C + c + 3) * 132 + r] = vv.w;
        }
    }
    __syncthreads();

    u64 acc[4][8];
    float v[8][8];

    // L1
    smem_gemm(at, wa, K1, tx, ty, acc);
    __syncthreads();
    unpack_epi(acc, b1, tx, 0, v);
    store_at_T(at, v, tx, ty);
    for (int i = tid; i < 4096; i += 256)        // wa <- W3
        ((float4*)wa)[i] = ((const float4*)W3)[i];
    __syncthreads();

    // L2
    smem_gemm(at, wb, 128, tx, ty, acc);
    __syncthreads();
    unpack_epi(acc, b2, tx, 0, v);
    store_at_T(at, v, tx, ty);
    for (int i = tid; i < 4096; i += 256)        // wb <- W4
        ((float4*)wb)[i] = ((const float4*)W4)[i];
    __syncthreads();

    // L3
    smem_gemm(at, wa, 128, tx, ty, acc);
    __syncthreads();
    unpack_epi(acc, b3, tx, MIX34, v);
    store_at_T(at, v, tx, ty);
    __syncthreads();

    // L4
    smem_gemm(at, wb, 128, tx, ty, acc);
    __syncthreads();
    unpack_epi(acc, b4, tx, MIX34, v);
    store_at_T(at, v, tx, ty);
    __syncthreads();

    // Wih projection: 4 chunks of 128 columns, output fp16
#pragma unroll 1
    for (int nc = 0; nc < 4; nc++) {
        for (int i = tid; i < 4096; i += 256) {
            int k  = i >> 5;
            int c4 = i & 31;
            ((float4*)wa)[i] = ((const float4*)Wih)[k * 128 + nc * 32 + c4];
        }
        __syncthreads();
        smem_gemm(at, wa, 128, tx, ty, acc);
        // epilogue: +bias, no relu, fp16 store
        float bv[8];
        *(float4*)&bv[0] = *(const float4*)&bih[nc * 128 + tx];
        *(float4*)&bv[4] = *(const float4*)&bih[nc * 128 + tx + 4];
#pragma unroll
        for (int i = 0; i < 4; i++)
#pragma unroll
            for (int j = 0; j < 8; j++)
                up2(v[2 * i][j], v[2 * i + 1][j], acc[i][j]);
#pragma unroll
        for (int r = 0; r < 8; r++) {
            __half2 h4[4];
#pragma unroll
            for (int j2 = 0; j2 < 4; j2++)
                h4[j2] = __floats2half2_rn(v[r][2*j2] + bv[2*j2],
                                           v[r][2*j2+1] + bv[2*j2+1]);
            __half* q = xz + (bm + ty + r) * 512 + nc * 128 + tx;
            *(uint4*)q = *(uint4*)h4;
        }
        __syncthreads();   // before wa overwrite next iter
    }
}

// ---------------------------------------------------------------------------
// LSTM v4: 512 threads, f32x2 matmul, fp16 xz, MUFU-free exp + fused rcp.
// Blocks 0..25: node (128 seqs), 26..128: edge (512 seqs). SPB=5.
// ---------------------------------------------------------------------------
__global__ __launch_bounds__(512, 1) void lstm4(
    const __half* __restrict__ xz_n, const float* __restrict__ Whh_n, float* __restrict__ hn,
    const __half* __restrict__ xz_e, const float* __restrict__ Whh_e, float* __restrict__ he)
{
    extern __shared__ float sm[];
    float* ws   = sm;                    // 96*512
    float* hdup = ws + 96 * 512;         // SPB*256
    float* csm  = hdup + SPB * 256;      // SPB*128
    float* zsm  = csm + SPB * 128;       // SPB*512

    const int tid = threadIdx.x;
    const int sub = tid >> 8;
    const int lt  = tid & 255;
    const int c2  = 2 * lt;
    const int i0  = sub ? 3 : 0;
    const int ni  = sub ? 2 : 3;

    const float* Whh;
    const __half* xz;
    float* out;
    int seq0, nseq;
    int is_node;

    if (blockIdx.x < 26) {
        Whh = Whh_n; xz = xz_n; out = hn;
        seq0 = blockIdx.x * SPB; nseq = 128; is_node = 1;
    } else {
        Whh = Whh_e; xz = xz_e; out = he;
        seq0 = (blockIdx.x - 26) * SPB; nseq = 512; is_node = 0;
    }
    const long xstep = is_node ? (4 * 512) : (16 * 512);   // half elements
    const long ostep = is_node ? (4 * 128) : (16 * 128);   // float elements

    const __half* xp[3];
    int valid[3];
#pragma unroll
    for (int j = 0; j < 3; j++) {
        int sq = seq0 + i0 + j;
        valid[j] = (j < ni) && (sq < nseq);
        long row = is_node ? ((long)(sq >> 2) * 2048 + (sq & 3))
                           : ((long)(sq >> 4) * 8192 + (sq & 15));
        xp[j] = xz + row * 512 + c2;
    }

    for (int idx = tid; idx < (96 * 512) / 4; idx += 512)
        ((float4*)ws)[idx] = ((const float4*)Whh)[idx];
    u64 wr[32];
#pragma unroll
    for (int r = 0; r < 32; r++)
        wr[r] = *(const u64*)&Whh[(96 + r) * 512 + c2];

    for (int idx = tid; idx < SPB * 256; idx += 512) hdup[idx] = 0.f;
    for (int idx = tid; idx < SPB * 128; idx += 512) csm[idx] = 0.f;
    __syncthreads();

    unsigned xr0 = valid[0] ? *(const unsigned*)(xp[0]) : 0u;
    unsigned xr1 = valid[1] ? *(const unsigned*)(xp[1]) : 0u;
    unsigned xr2 = valid[2] ? *(const unsigned*)(xp[2]) : 0u;

    for (int t = 0; t < 512; t++) {
        u64 acc0 = 0ull, acc1 = 0ull, acc2 = 0ull;
        const float* hb = hdup + i0 * 256;

#pragma unroll 4
        for (int k = 0; k < 96; k += 2) {
            u64 w0 = *(const u64*)&ws[(size_t)k * 512 + c2];
            u64 w1 = *(const u64*)&ws[(size_t)(k + 1) * 512 + c2];
            ulonglong2 h0 = *(const ulonglong2*)(hb + 2 * k);
            ulonglong2 h1 = *(const ulonglong2*)(hb + 256 + 2 * k);
            fma2(acc0, h0.x, w0); fma2(acc0, h0.y, w1);
            fma2(acc1, h1.x, w0); fma2(acc1, h1.y, w1);
            if (ni == 3) {
                ulonglong2 h2 = *(const ulonglong2*)(hb + 512 + 2 * k);
                fma2(acc2, h2.x, w0); fma2(acc2, h2.y, w1);
            }
        }
#pragma unroll
        for (int r = 0; r < 32; r += 2) {
            ulonglong2 h0 = *(const ulonglong2*)(hb + 192 + 2 * r);
            ulonglong2 h1 = *(const ulonglong2*)(hb + 256 + 192 + 2 * r);
            fma2(acc0, h0.x, wr[r]); fma2(acc0, h0.y, wr[r + 1]);
            fma2(acc1, h1.x, wr[r]); fma2(acc1, h1.y, wr[r + 1]);
            if (ni == 3) {
                ulonglong2 h2 = *(const ulonglong2*)(hb + 512 + 192 + 2 * r);
                fma2(acc2, h2.x, wr[r]); fma2(acc2, h2.y, wr[r + 1]);
            }
        }

        {   // z = acc + xz (fp16 -> fp32)
            float2 f0 = __half22float2(*(const __half2*)&xr0);
            float2 f1 = __half22float2(*(const __half2*)&xr1);
            *(u64*)&zsm[(i0 + 0) * 512 + c2] = add2(acc0, pk2(f0.x, f0.y));
            *(u64*)&zsm[(i0 + 1) * 512 + c2] = add2(acc1, pk2(f1.x, f1.y));
            if (ni == 3) {
                float2 f2 = __half22float2(*(const __half2*)&xr2);
                *(u64*)&zsm[(i0 + 2) * 512 + c2] = add2(acc2, pk2(f2.x, f2.y));
            }
        }

        int tn = (t + 1 < 512) ? (t + 1) : t;
        xr0 = valid[0] ? *(const unsigned*)(xp[0] + tn * xstep) : 0u;
        xr1 = valid[1] ? *(const unsigned*)(xp[1] + tn * xstep) : 0u;
        xr2 = valid[2] ? *(const unsigned*)(xp[2] + tn * xstep) : 0u;

        __syncthreads();

        // gates: 2 MUFU (rcp) per element, exp on FMA pipe
        for (int q = tid; q < SPB * 128; q += 512) {
            int i = q >> 7, hh = q & 127;
            const float* zrow = zsm + i * 512;
            float zi = clamp15(zrow[hh]);
            float zf = clamp15(zrow[128 + hh]);
            float zg = clamp15(zrow[256 + hh]);
            float zo = clamp15(zrow[384 + hh]);
            float ei = pexp(-zi);
            float ef = pexp(-zf);
            float g2 = pexp(2.0f * zg);
            float eo = pexp(-zo);
            float pi_ = 1.f + ei, pf_ = 1.f + ef, pg_ = g2 + 1.f;
            float cold = csm[q];
            // c' = sig(zf)*c + sig(zi)*tanh(zg), fused over common denominator
            float num = cold * pi_ * pg_ + (g2 - 1.f) * pf_;
            float cn  = num * rcpa(pf_ * pi_ * pg_);
            float cc  = clamp15(cn);
            float T   = pexp(2.0f * cc);
            float hv  = (T - 1.f) * rcpa((T + 1.f) * (1.f + eo));
            csm[q] = cn;
            float2 hp; hp.x = hv; hp.y = hv;
            *(float2*)&hdup[i * 256 + 2 * hh] = hp;
            int sq = seq0 + i;
            if (sq < nseq) {
                long row = is_node ? ((long)(sq >> 2) * 2048 + (sq & 3))
                                   : ((long)(sq >> 4) * 8192 + (sq & 15));
                out[row * 128 + (long)t * ostep + hh] = hv;
            }
        }
        __syncthreads();
    }
}

// ---------------------------------------------------------------------------
// Classifier fused: gather(src,dst,he) @ Wc1 + bc1 -> relu -> @ Wc2 + bc2
// ---------------------------------------------------------------------------
__global__ __launch_bounds__(256) void c1final(
    const float* __restrict__ hn, const float* __restrict__ he,
    const float* __restrict__ Wc1, const float* __restrict__ bc1,
    const float* __restrict__ Wc2, const float* __restrict__ bc2,
    float* __restrict__ out)
{
    extern __shared__ float s[];
    float* As  = s;              // 16 * 68
    float* Bs  = As + 16 * 68;   // 16 * 256
    float* ct  = Bs + 16 * 256;  // 256 * 68
    float* wc2 = ct + 256 * 68;  // 256 * 8
    const int tid = threadIdx.x;
    const long bm = (long)blockIdx.x * 64;
    const int tx = (tid & 31) * 8;
    const int ty = (tid >> 5) * 8;

    for (int i = tid; i < 512; i += 256)
        ((float4*)wc2)[i] = ((const float4*)Wc2)[i];

    const int arow = tid >> 2;
    const int acol = (tid & 3) * 4;
    const long row = bm + arow;
    const long bt  = row >> 4;
    const int  e   = (int)(row & 15);
    const float* seg0 = hn + (bt * 4 + (e >> 2)) * 128;
    const float* seg1 = hn + (bt * 4 + (e & 3)) * 128;
    const float* seg2 = he + row * 128;

    const int brow = tid >> 4;
    const int bcol = (tid & 15) * 16;

    u64 acc[4][8];
#pragma unroll
    for (int i = 0; i < 4; i++)
#pragma unroll
        for (int j = 0; j < 8; j++) acc[i][j] = 0ull;

    for (int k0 = 0; k0 < 384; k0 += 16) {
        const float* sp = (k0 < 128) ? seg0 : ((k0 < 256) ? seg1 : seg2);
        float4 av = *(const float4*)(sp + (k0 & 127) + acol);
        const float* bp = Wc1 + (size_t)(k0 + brow) * 256 + bcol;
        float4 bv0 = *(const float4*)(bp);
        float4 bv1 = *(const float4*)(bp + 4);
        float4 bv2 = *(const float4*)(bp + 8);
        float4 bv3 = *(const float4*)(bp + 12);
        As[(acol + 0) * 68 + arow] = av.x;
        As[(acol + 1) * 68 + arow] = av.y;
        As[(acol + 2) * 68 + arow] = av.z;
        As[(acol + 3) * 68 + arow] = av.w;
        float* bq = Bs + brow * 256 + bcol;
        *(float4*)(bq)      = bv0;
        *(float4*)(bq + 4)  = bv1;
        *(float4*)(bq + 8)  = bv2;
        *(float4*)(bq + 12) = bv3;
        __syncthreads();

#pragma unroll
        for (int kk = 0; kk < 16; kk++) {
            ulonglong2 aa = *(const ulonglong2*)&As[kk * 68 + ty];
            ulonglong2 ab = *(const ulonglong2*)&As[kk * 68 + ty + 4];
            float4 c0 = *(const float4*)&Bs[kk * 256 + tx];
            float4 c1 = *(const float4*)&Bs[kk * 256 + tx + 4];
            u64 bd[8];
            bd[0] = pk2(c0.x, c0.x); bd[1] = pk2(c0.y, c0.y);
            bd[2] = pk2(c0.z, c0.z); bd[3] = pk2(c0.w, c0.w);
            bd[4] = pk2(c1.x, c1.x); bd[5] = pk2(c1.y, c1.y);
            bd[6] = pk2(c1.z, c1.z); bd[7] = pk2(c1.w, c1.w);
            u64 ap[4] = { aa.x, aa.y, ab.x, ab.y };
#pragma unroll
            for (int i = 0; i < 4; i++)
#pragma unroll
                for (int j = 0; j < 8; j++)
                    fma2(acc[i][j], ap[i], bd[j]);
        }
        __syncthreads();
    }

    float v[8][8];
#pragma unroll
    for (int i = 0; i < 4; i++)
#pragma unroll
        for (int j = 0; j < 8; j++)
            up2(v[2 * i][j], v[2 * i + 1][j], acc[i][j]);
    float bv[8];
    *(float4*)&bv[0] = *(const float4*)&bc1[tx];
    *(float4*)&bv[4] = *(const float4*)&bc1[tx + 4];
#pragma unroll
    for (int j = 0; j < 8; j++) {
        float* q = ct + (tx + j) * 68 + ty;
        *(float4*)(q)     = make_float4(fmaxf(v[0][j]+bv[j],0.f), fmaxf(v[1][j]+bv[j],0.f),
                                        fmaxf(v[2][j]+bv[j],0.f), fmaxf(v[3][j]+bv[j],0.f));
        *(float4*)(q + 4) = make_float4(fmaxf(v[4][j]+bv[j],0.f), fmaxf(v[5][j]+bv[j],0.f),
                                        fmaxf(v[6][j]+bv[j],0.f), fmaxf(v[7][j]+bv[j],0.f));
    }
    __syncthreads();

    {
        const int r = tid >> 2;
        const int c = (tid & 3) * 2;
        float f0 = bc2[c], f1 = bc2[c + 1];
#pragma unroll 8
        for (int k = 0; k < 256; k++) {
            float a = ct[k * 68 + r];
            f0 += a * wc2[k * 8 + c];
            f1 += a * wc2[k * 8 + c + 1];
        }
        float* q = out + (bm + r) * 8 + c;
        q[0] = f0; q[1] = f1;
    }
}

// ---------------------------------------------------------------------------
// Launch: just 4 kernels. (Profiled slot idx3 = c1final.)
// ---------------------------------------------------------------------------
extern "C" void kernel_launch(void* const* d_in, const int* in_sizes, int n_in,
                              void* d_out, int out_size)
{
    const float* x_seq = (const float*)d_in[0];
    const float* ea    = (const float*)d_in[1];
    const float* Wn1   = (const float*)d_in[2];
    const float* bn1   = (const float*)d_in[3];
    const float* Wn2   = (const float*)d_in[4];
    const float* bn2   = (const float*)d_in[5];
    const float* We1   = (const float*)d_in[6];
    const float* be1   = (const float*)d_in[7];
    const float* We2   = (const float*)d_in[8];
    const float* be2   = (const float*)d_in[9];
    const float* Wg1   = (const float*)d_in[10];
    const float* bg1   = (const float*)d_in[11];
    const float* Wg2   = (const float*)d_in[12];
    const float* bg2   = (const float*)d_in[13];
    const float* Wef1  = (const float*)d_in[14];
    const float* bef1  = (const float*)d_in[15];
    const float* Wef2  = (const float*)d_in[16];
    const float* bef2  = (const float*)d_in[17];
    const float* Wih_n = (const float*)d_in[18];
    const float* Whh_n = (const float*)d_in[19];
    const float* b_n   = (const float*)d_in[20];
    const float* Wih_e = (const float*)d_in[21];
    const float* Whh_e = (const float*)d_in[22];
    const float* b_e   = (const float*)d_in[23];
    const float* Wc1   = (const float*)d_in[24];
    const float* bc1   = (const float*)d_in[25];
    const float* Wc2   = (const float*)d_in[26];
    const float* bc2   = (const float*)d_in[27];
    float* out = (float*)d_out;

    (void)in_sizes; (void)n_in; (void)out_size;

    const int SMF   = (128*128*2 + 128*132) * 4;                 // 198656
    const int SMC1F = (16*68 + 16*256 + 256*68 + 256*8) * 4;     // 98560
    cudaFuncSetAttribute(fused_all<8,0>,  cudaFuncAttributeMaxDynamicSharedMemorySize, SMF);
    cudaFuncSetAttribute(fused_all<16,1>, cudaFuncAttributeMaxDynamicSharedMemorySize, SMF);
    cudaFuncSetAttribute(lstm4,   cudaFuncAttributeMaxDynamicSharedMemorySize, LSTM_SMEM_BYTES);
    cudaFuncSetAttribute(c1final, cudaFuncAttributeMaxDynamicSharedMemorySize, SMC1F);

    __half* xze_h = (__half*)(g_arena + OFF_XZE_H);
    __half* xzn_h = (__half*)(g_arena + OFF_XZN_H);
    float*  hn    = g_arena + OFF_HN;
    float*  he    = g_arena + OFF_HE;

    // idx0: edge path ea -> xze (fp16)
    fused_all<8,0><<<2048, 256, SMF>>>(ea,
        We1, be1, We2, be2, Wef1, bef1, Wef2, bef2, Wih_e, b_e, xze_h);
    // idx1: node path x_seq -> xzn (fp16), graph-conv mixes on layers 3,4
    fused_all<16,1><<<512, 256, SMF>>>(x_seq,
        Wn1, bn1, Wn2, bn2, Wg1, bg1, Wg2, bg2, Wih_n, b_n, xzn_h);
    // idx2: fused LSTM -> hn, he
    lstm4<<<129, 512, LSTM_SMEM_BYTES>>>(xzn_h, Whh_n, hn, xze_h, Whh_e, he);
    // idx3: classifier (profiled)
    c1final<<<4096, 256, SMC1F>>>(hn, he, Wc1, bc1, Wc2, bc2, out);
}

// round 6
// speedup vs baseline: 5.4182x; 1.0324x over previous
#include <cuda_runtime.h>
#include <cuda_fp16.h>
#include <math.h>

// ---------------------------------------------------------------------------
// Problem: B=32,T=512,N=4,E=16, NI=16,EI=8, HN=HE=128, MH=256, C=8
// M_node=65536, M_edge=262144
// HW model (measured r4/r5): __device__ statics are HOST-resident via
// NVLink-C2C (~230 GB/s, L2-bypassed). Arena bytes are the currency.
// ---------------------------------------------------------------------------

typedef unsigned long long u64;

#define SPB 5
#define LSTM_SMEM_FLOATS (96*512 + SPB*256 + SPB*128 + SPB*512)
#define LSTM_SMEM_BYTES  (LSTM_SMEM_FLOATS * 4)

// ---- scratch arena (host-resident): 419MB ----
// xze fp16: 262144*512 -> 67108864 float-slots
// xzn fp16: 65536*512  -> 16777216
// hn  fp16: 65536*128  ->  4194304
// he  fp16: 262144*128 -> 16777216
#define OFF_XZE_H 0L
#define OFF_XZN_H 67108864L
#define OFF_HN    83886080L
#define OFF_HE    88080384L
__device__ float g_arena[104857600];

// ---- packed fp32x2 helpers ----
__device__ __forceinline__ u64 pk2(float lo, float hi) {
    u64 r; asm("mov.b64 %0, {%1,%2};" : "=l"(r) : "f"(lo), "f"(hi)); return r;
}
__device__ __forceinline__ void up2(float& lo, float& hi, u64 v) {
    asm("mov.b64 {%0,%1}, %2;" : "=f"(lo), "=f"(hi) : "l"(v));
}
__device__ __forceinline__ void fma2(u64& c, u64 a, u64 b) {
    asm("fma.rn.f32x2 %0, %1, %2, %0;" : "+l"(c) : "l"(a), "l"(b));
}
__device__ __forceinline__ u64 add2(u64 a, u64 b) {
    u64 r; asm("add.rn.f32x2 %0, %1, %2;" : "=l"(r) : "l"(a), "l"(b)); return r;
}

// ---- MUFU-free exp (FMA pipe only), err ~1e-7 for |x|<=~40 ----
__device__ __forceinline__ float pexp(float x) {
    float t = x * 1.44269504088896f;
    float k = t + 12582912.0f;
    int   e = __float_as_int(k) - 0x4B400000;
    float n = k - 12582912.0f;
    float f = t - n;
    float p =              1.54035304e-4f;
    p = fmaf(p, f, 1.33335581e-3f);
    p = fmaf(p, f, 9.61812911e-3f);
    p = fmaf(p, f, 5.55041087e-2f);
    p = fmaf(p, f, 2.40226507e-1f);
    p = fmaf(p, f, 6.93147181e-1f);
    p = fmaf(p, f, 1.0f);
    float s = __int_as_float((e + 127) << 23);
    return p * s;
}
__device__ __forceinline__ float rcpa(float x) {
    float r; asm("rcp.approx.f32 %0, %1;" : "=f"(r) : "f"(x)); return r;
}
__device__ __forceinline__ float clamp15(float x) {
    return fminf(fmaxf(x, -15.f), 15.f);
}

// ---------------------------------------------------------------------------
// SMEM microtile GEMM: at[k*132+r] (transposed activations), w[k*128+c]
// ---------------------------------------------------------------------------
__device__ __forceinline__ void smem_gemm(
    const float* at, const float* w, int K, int tx, int ty, u64 acc[4][8])
{
#pragma unroll
    for (int i = 0; i < 4; i++)
#pragma unroll
        for (int j = 0; j < 8; j++) acc[i][j] = 0ull;
#pragma unroll 8
    for (int k = 0; k < K; k++) {
        ulonglong2 aa = *(const ulonglong2*)&at[k * 132 + ty];
        ulonglong2 ab = *(const ulonglong2*)&at[k * 132 + ty + 4];
        float4 c0 = *(const float4*)&w[k * 128 + tx];
        float4 c1 = *(const float4*)&w[k * 128 + tx + 4];
        u64 bd[8];
        bd[0] = pk2(c0.x, c0.x); bd[1] = pk2(c0.y, c0.y);
        bd[2] = pk2(c0.z, c0.z); bd[3] = pk2(c0.w, c0.w);
        bd[4] = pk2(c1.x, c1.x); bd[5] = pk2(c1.y, c1.y);
        bd[6] = pk2(c1.z, c1.z); bd[7] = pk2(c1.w, c1.w);
        u64 ap[4] = { aa.x, aa.y, ab.x, ab.y };
#pragma unroll
        for (int i = 0; i < 4; i++)
#pragma unroll
            for (int j = 0; j < 8; j++)
                fma2(acc[i][j], ap[i], bd[j]);
    }
}

__device__ __forceinline__ void unpack_epi(
    u64 acc[4][8], const float* bias, int tx, int MIX, float v[8][8])
{
#pragma unroll
    for (int i = 0; i < 4; i++)
#pragma unroll
        for (int j = 0; j < 8; j++)
            up2(v[2 * i][j], v[2 * i + 1][j], acc[i][j]);
    float bv[8];
    *(float4*)&bv[0] = *(const float4*)&bias[tx];
    *(float4*)&bv[4] = *(const float4*)&bias[tx + 4];
    if (MIX) {
#pragma unroll
        for (int g = 0; g < 2; g++) {
            float s[8];
#pragma unroll
            for (int j = 0; j < 8; j++)
                s[j] = v[4*g][j] + v[4*g+1][j] + v[4*g+2][j] + v[4*g+3][j];
#pragma unroll
            for (int r = 0; r < 4; r++)
#pragma unroll
                for (int j = 0; j < 8; j++)
                    v[4*g+r][j] = fmaxf((s[j] + v[4*g+r][j]) * 0.2f + bv[j], 0.f);
        }
    } else {
#pragma unroll
        for (int r = 0; r < 8; r++)
#pragma unroll
            for (int j = 0; j < 8; j++)
                v[r][j] = fmaxf(v[r][j] + bv[j], 0.f);
    }
}

__device__ __forceinline__ void store_at_T(float* at, float v[8][8], int tx, int ty)
{
#pragma unroll
    for (int j = 0; j < 8; j++) {
        float* q = at + (tx + j) * 132 + ty;
        *(float4*)(q)     = make_float4(v[0][j], v[1][j], v[2][j], v[3][j]);
        *(float4*)(q + 4) = make_float4(v[4][j], v[5][j], v[6][j], v[7][j]);
    }
}

// ---------------------------------------------------------------------------
// Whole feed-forward path in ONE kernel: in -> L1..L4 -> Wih -> xz (fp16).
// ---------------------------------------------------------------------------
template <int K1, int MIX34>
__global__ __launch_bounds__(256) void fused_all(
    const float* __restrict__ in,
    const float* __restrict__ W1, const float* __restrict__ b1,
    const float* __restrict__ W2, const float* __restrict__ b2,
    const float* __restrict__ W3, const float* __restrict__ b3,
    const float* __restrict__ W4, const float* __restrict__ b4,
    const float* __restrict__ Wih, const float* __restrict__ bih,
    __half* __restrict__ xz)
{
    extern __shared__ float s[];
    float* wa = s;                 // 128*128
    float* wb = wa + 128 * 128;    // 128*128
    float* at = wb + 128 * 128;    // 128*132
    const int tid = threadIdx.x;
    const long bm = (long)blockIdx.x * 128;
    const int tx = (tid & 15) * 8;
    const int ty = (tid >> 4) * 8;

    for (int i = tid; i < K1 * 32; i += 256)
        ((float4*)wa)[i] = ((const float4*)W1)[i];
    for (int i = tid; i < 4096; i += 256)
        ((float4*)wb)[i] = ((const float4*)W2)[i];
    {
        const int r = tid >> 1;
        const int h = tid & 1;
        const int C = K1 / 2;
        const float* p = in + (bm + r) * K1 + h * C;
#pragma unroll
        for (int c = 0; c < C; c += 4) {
            float4 vv = *(const float4*)(p + c);
            at[(h * C + c + 0) * 132 + r] = vv.x;
            at[(h * C + c + 1) * 132 + r] = vv.y;
            at[(h * C + c + 2) * 132 + r] = vv.z;
            at[(h * C + c + 3) * 132 + r] = vv.w;
        }
    }
    __syncthreads();

    u64 acc[4][8];
    float v[8][8];

    // L1
    smem_gemm(at, wa, K1, tx, ty, acc);
    __syncthreads();
    unpack_epi(acc, b1, tx, 0, v);
    store_at_T(at, v, tx, ty);
    for (int i = tid; i < 4096; i += 256)
        ((float4*)wa)[i] = ((const float4*)W3)[i];
    __syncthreads();

    // L2
    smem_gemm(at, wb, 128, tx, ty, acc);
    __syncthreads();
    unpack_epi(acc, b2, tx, 0, v);
    store_at_T(at, v, tx, ty);
    for (int i = tid; i < 4096; i += 256)
        ((float4*)wb)[i] = ((const float4*)W4)[i];
    __syncthreads();

    // L3
    smem_gemm(at, wa, 128, tx, ty, acc);
    __syncthreads();
    unpack_epi(acc, b3, tx, MIX34, v);
    store_at_T(at, v, tx, ty);
    __syncthreads();

    // L4
    smem_gemm(at, wb, 128, tx, ty, acc);
    __syncthreads();
    unpack_epi(acc, b4, tx, MIX34, v);
    store_at_T(at, v, tx, ty);
    __syncthreads();

    // Wih projection: 4 chunks of 128 columns, fp16 out
#pragma unroll 1
    for (int nc = 0; nc < 4; nc++) {
        for (int i = tid; i < 4096; i += 256) {
            int k  = i >> 5;
            int c4 = i & 31;
            ((float4*)wa)[i] = ((const float4*)Wih)[k * 128 + nc * 32 + c4];
        }
        __syncthreads();
        smem_gemm(at, wa, 128, tx, ty, acc);
        float bv[8];
        *(float4*)&bv[0] = *(const float4*)&bih[nc * 128 + tx];
        *(float4*)&bv[4] = *(const float4*)&bih[nc * 128 + tx + 4];
#pragma unroll
        for (int i = 0; i < 4; i++)
#pragma unroll
            for (int j = 0; j < 8; j++)
                up2(v[2 * i][j], v[2 * i + 1][j], acc[i][j]);
#pragma unroll
        for (int r = 0; r < 8; r++) {
            __half2 h4[4];
#pragma unroll
            for (int j2 = 0; j2 < 4; j2++)
                h4[j2] = __floats2half2_rn(v[r][2*j2] + bv[2*j2],
                                           v[r][2*j2+1] + bv[2*j2+1]);
            __half* q = xz + (bm + ty + r) * 512 + nc * 128 + tx;
            *(uint4*)q = *(uint4*)h4;
        }
        __syncthreads();
    }
}

// ---------------------------------------------------------------------------
// LSTM: 512 threads, f32x2 matmul, fp16 xz in, fp16 h out (state stays fp32).
// ---------------------------------------------------------------------------
__global__ __launch_bounds__(512, 1) void lstm4(
    const __half* __restrict__ xz_n, const float* __restrict__ Whh_n, __half* __restrict__ hn,
    const __half* __restrict__ xz_e, const float* __restrict__ Whh_e, __half* __restrict__ he)
{
    extern __shared__ float sm[];
    float* ws   = sm;                    // 96*512
    float* hdup = ws + 96 * 512;         // SPB*256
    float* csm  = hdup + SPB * 256;      // SPB*128
    float* zsm  = csm + SPB * 128;       // SPB*512

    const int tid = threadIdx.x;
    const int sub = tid >> 8;
    const int lt  = tid & 255;
    const int c2  = 2 * lt;
    const int i0  = sub ? 3 : 0;
    const int ni  = sub ? 2 : 3;

    const float* Whh;
    const __half* xz;
    __half* out;
    int seq0, nseq;
    int is_node;

    if (blockIdx.x < 26) {
        Whh = Whh_n; xz = xz_n; out = hn;
        seq0 = blockIdx.x * SPB; nseq = 128; is_node = 1;
    } else {
        Whh = Whh_e; xz = xz_e; out = he;
        seq0 = (blockIdx.x - 26) * SPB; nseq = 512; is_node = 0;
    }
    const long xstep = is_node ? (4 * 512) : (16 * 512);
    const long ostep = is_node ? (4 * 128) : (16 * 128);

    const __half* xp[3];
    int valid[3];
#pragma unroll
    for (int j = 0; j < 3; j++) {
        int sq = seq0 + i0 + j;
        valid[j] = (j < ni) && (sq < nseq);
        long row = is_node ? ((long)(sq >> 2) * 2048 + (sq & 3))
                           : ((long)(sq >> 4) * 8192 + (sq & 15));
        xp[j] = xz + row * 512 + c2;
    }

    for (int idx = tid; idx < (96 * 512) / 4; idx += 512)
        ((float4*)ws)[idx] = ((const float4*)Whh)[idx];
    u64 wr[32];
#pragma unroll
    for (int r = 0; r < 32; r++)
        wr[r] = *(const u64*)&Whh[(96 + r) * 512 + c2];

    for (int idx = tid; idx < SPB * 256; idx += 512) hdup[idx] = 0.f;
    for (int idx = tid; idx < SPB * 128; idx += 512) csm[idx] = 0.f;
    __syncthreads();

    unsigned xr0 = valid[0] ? *(const unsigned*)(xp[0]) : 0u;
    unsigned xr1 = valid[1] ? *(const unsigned*)(xp[1]) : 0u;
    unsigned xr2 = valid[2] ? *(const unsigned*)(xp[2]) : 0u;

    for (int t = 0; t < 512; t++) {
        u64 acc0 = 0ull, acc1 = 0ull, acc2 = 0ull;
        const float* hb = hdup + i0 * 256;

#pragma unroll 4
        for (int k = 0; k < 96; k += 2) {
            u64 w0 = *(const u64*)&ws[(size_t)k * 512 + c2];
            u64 w1 = *(const u64*)&ws[(size_t)(k + 1) * 512 + c2];
            ulonglong2 h0 = *(const ulonglong2*)(hb + 2 * k);
            ulonglong2 h1 = *(const ulonglong2*)(hb + 256 + 2 * k);
            fma2(acc0, h0.x, w0); fma2(acc0, h0.y, w1);
            fma2(acc1, h1.x, w0); fma2(acc1, h1.y, w1);
            if (ni == 3) {
                ulonglong2 h2 = *(const ulonglong2*)(hb + 512 + 2 * k);
                fma2(acc2, h2.x, w0); fma2(acc2, h2.y, w1);
            }
        }
#pragma unroll
        for (int r = 0; r < 32; r += 2) {
            ulonglong2 h0 = *(const ulonglong2*)(hb + 192 + 2 * r);
            ulonglong2 h1 = *(const ulonglong2*)(hb + 256 + 192 + 2 * r);
            fma2(acc0, h0.x, wr[r]); fma2(acc0, h0.y, wr[r + 1]);
            fma2(acc1, h1.x, wr[r]); fma2(acc1, h1.y, wr[r + 1]);
            if (ni == 3) {
                ulonglong2 h2 = *(const ulonglong2*)(hb + 512 + 192 + 2 * r);
                fma2(acc2, h2.x, wr[r]); fma2(acc2, h2.y, wr[r + 1]);
            }
        }

        {
            float2 f0 = __half22float2(*(const __half2*)&xr0);
            float2 f1 = __half22float2(*(const __half2*)&xr1);
            *(u64*)&zsm[(i0 + 0) * 512 + c2] = add2(acc0, pk2(f0.x, f0.y));
            *(u64*)&zsm[(i0 + 1) * 512 + c2] = add2(acc1, pk2(f1.x, f1.y));
            if (ni == 3) {
                float2 f2 = __half22float2(*(const __half2*)&xr2);
                *(u64*)&zsm[(i0 + 2) * 512 + c2] = add2(acc2, pk2(f2.x, f2.y));
            }
        }

        int tn = (t + 1 < 512) ? (t + 1) : t;
        xr0 = valid[0] ? *(const unsigned*)(xp[0] + tn * xstep) : 0u;
        xr1 = valid[1] ? *(const unsigned*)(xp[1] + tn * xstep) : 0u;
        xr2 = valid[2] ? *(const unsigned*)(xp[2] + tn * xstep) : 0u;

        __syncthreads();

        for (int q = tid; q < SPB * 128; q += 512) {
            int i = q >> 7, hh = q & 127;
            const float* zrow = zsm + i * 512;
            float zi = clamp15(zrow[hh]);
            float zf = clamp15(zrow[128 + hh]);
            float zg = clamp15(zrow[256 + hh]);
            float zo = clamp15(zrow[384 + hh]);
            float ei = pexp(-zi);
            float ef = pexp(-zf);
            float g2 = pexp(2.0f * zg);
            float eo = pexp(-zo);
            float pi_ = 1.f + ei, pf_ = 1.f + ef, pg_ = g2 + 1.f;
            float cold = csm[q];
            float num = cold * pi_ * pg_ + (g2 - 1.f) * pf_;
            float cn  = num * rcpa(pf_ * pi_ * pg_);
            float cc  = clamp15(cn);
            float T   = pexp(2.0f * cc);
            float hv  = (T - 1.f) * rcpa((T + 1.f) * (1.f + eo));
            csm[q] = cn;
            float2 hp; hp.x = hv; hp.y = hv;
            *(float2*)&hdup[i * 256 + 2 * hh] = hp;
            int sq = seq0 + i;
            if (sq < nseq) {
                long row = is_node ? ((long)(sq >> 2) * 2048 + (sq & 3))
                                   : ((long)(sq >> 4) * 8192 + (sq & 15));
                out[row * 128 + (long)t * ostep + hh] = __float2half(hv);
            }
        }
        __syncthreads();
    }
}

// ---------------------------------------------------------------------------
// Classifier fused, fp16 h inputs. Block = 64 rows = 4 bt groups.
// The 16 hn rows a block needs are CONTIGUOUS (bt0*4 .. bt0*4+15): staged
// once into SMEM (fp32), killing the 8x redundant arena gather traffic.
// ---------------------------------------------------------------------------
__global__ __launch_bounds__(256) void c1final(
    const __half* __restrict__ hn, const __half* __restrict__ he,
    const float* __restrict__ Wc1, const float* __restrict__ bc1,
    const float* __restrict__ Wc2, const float* __restrict__ bc2,
    float* __restrict__ out)
{
    extern __shared__ float s[];
    float* hn_s = s;               // 16*128
    float* As   = hn_s + 2048;     // 16*68
    float* Bs   = As + 16 * 68;    // 16*256
    float* ct   = Bs + 16 * 256;   // 256*68
    float* wc2  = ct + 256 * 68;   // 256*8
    const int tid = threadIdx.x;
    const long bm = (long)blockIdx.x * 64;
    const int tx = (tid & 31) * 8;
    const int ty = (tid >> 5) * 8;

    for (int i = tid; i < 512; i += 256)
        ((float4*)wc2)[i] = ((const float4*)Wc2)[i];

    // stage the block's 16 contiguous hn rows (fp16 -> fp32 SMEM)
    {
        const long bt0 = bm >> 4;
        const __half* hp = hn + bt0 * 4 * 128 + tid * 8;
        uint4 raw = *(const uint4*)hp;
        const __half2* h2p = (const __half2*)&raw;
        float* q = hn_s + tid * 8;
#pragma unroll
        for (int j = 0; j < 4; j++) {
            float2 f = __half22float2(h2p[j]);
            q[2*j] = f.x; q[2*j+1] = f.y;
        }
    }

    const int arow = tid >> 2;          // 0..63
    const int acol = (tid & 3) * 4;
    const long row = bm + arow;
    const int  e   = arow & 15;
    const int  g   = arow >> 4;         // local bt
    const float* seg0 = hn_s + (g * 4 + (e >> 2)) * 128;
    const float* seg1 = hn_s + (g * 4 + (e & 3)) * 128;
    const __half* seg2 = he + row * 128;

    const int brow = tid >> 4;
    const int bcol = (tid & 15) * 16;

    u64 acc[4][8];
#pragma unroll
    for (int i = 0; i < 4; i++)
#pragma unroll
        for (int j = 0; j < 8; j++) acc[i][j] = 0ull;

    __syncthreads();    // hn_s ready

    for (int k0 = 0; k0 < 384; k0 += 16) {
        float4 av;
        if (k0 < 128) {
            av = *(const float4*)(seg0 + k0 + acol);
        } else if (k0 < 256) {
            av = *(const float4*)(seg1 + (k0 - 128) + acol);
        } else {
            const __half* p = seg2 + (k0 - 256) + acol;
            uint2 raw = *(const uint2*)p;
            float2 f01 = __half22float2(*(const __half2*)&raw.x);
            float2 f23 = __half22float2(*(const __half2*)&raw.y);
            av = make_float4(f01.x, f01.y, f23.x, f23.y);
        }
        const float* bp = Wc1 + (size_t)(k0 + brow) * 256 + bcol;
        float4 bv0 = *(const float4*)(bp);
        float4 bv1 = *(const float4*)(bp + 4);
        float4 bv2 = *(const float4*)(bp + 8);
        float4 bv3 = *(const float4*)(bp + 12);
        As[(acol + 0) * 68 + arow] = av.x;
        As[(acol + 1) * 68 + arow] = av.y;
        As[(acol + 2) * 68 + arow] = av.z;
        As[(acol + 3) * 68 + arow] = av.w;
        float* bq = Bs + brow * 256 + bcol;
        *(float4*)(bq)      = bv0;
        *(float4*)(bq + 4)  = bv1;
        *(float4*)(bq + 8)  = bv2;
        *(float4*)(bq + 12) = bv3;
        __syncthreads();

#pragma unroll
        for (int kk = 0; kk < 16; kk++) {
            ulonglong2 aa = *(const ulonglong2*)&As[kk * 68 + ty];
            ulonglong2 ab = *(const ulonglong2*)&As[kk * 68 + ty + 4];
            float4 c0 = *(const float4*)&Bs[kk * 256 + tx];
            float4 c1 = *(const float4*)&Bs[kk * 256 + tx + 4];
            u64 bd[8];
            bd[0] = pk2(c0.x, c0.x); bd[1] = pk2(c0.y, c0.y);
            bd[2] = pk2(c0.z, c0.z); bd[3] = pk2(c0.w, c0.w);
            bd[4] = pk2(c1.x, c1.x); bd[5] = pk2(c1.y, c1.y);
            bd[6] = pk2(c1.z, c1.z); bd[7] = pk2(c1.w, c1.w);
            u64 ap[4] = { aa.x, aa.y, ab.x, ab.y };
#pragma unroll
            for (int i = 0; i < 4; i++)
#pragma unroll
                for (int j = 0; j < 8; j++)
                    fma2(acc[i][j], ap[i], bd[j]);
        }
        __syncthreads();
    }

    float v[8][8];
#pragma unroll
    for (int i = 0; i < 4; i++)
#pragma unroll
        for (int j = 0; j < 8; j++)
            up2(v[2 * i][j], v[2 * i + 1][j], acc[i][j]);
    float bv[8];
    *(float4*)&bv[0] = *(const float4*)&bc1[tx];
    *(float4*)&bv[4] = *(const float4*)&bc1[tx + 4];
#pragma unroll
    for (int j = 0; j < 8; j++) {
        float* q = ct + (tx + j) * 68 + ty;
        *(float4*)(q)     = make_float4(fmaxf(v[0][j]+bv[j],0.f), fmaxf(v[1][j]+bv[j],0.f),
                                        fmaxf(v[2][j]+bv[j],0.f), fmaxf(v[3][j]+bv[j],0.f));
        *(float4*)(q + 4) = make_float4(fmaxf(v[4][j]+bv[j],0.f), fmaxf(v[5][j]+bv[j],0.f),
                                        fmaxf(v[6][j]+bv[j],0.f), fmaxf(v[7][j]+bv[j],0.f));
    }
    __syncthreads();

    {
        const int r = tid >> 2;
        const int c = (tid & 3) * 2;
        float f0 = bc2[c], f1 = bc2[c + 1];
#pragma unroll 8
        for (int k = 0; k < 256; k++) {
            float a = ct[k * 68 + r];
            f0 += a * wc2[k * 8 + c];
            f1 += a * wc2[k * 8 + c + 1];
        }
        float* q = out + (bm + r) * 8 + c;
        q[0] = f0; q[1] = f1;
    }
}

// ---------------------------------------------------------------------------
// Launch: 4 kernels. (Profiled slot idx3 = c1final.)
// ---------------------------------------------------------------------------
extern "C" void kernel_launch(void* const* d_in, const int* in_sizes, int n_in,
                              void* d_out, int out_size)
{
    const float* x_seq = (const float*)d_in[0];
    const float* ea    = (const float*)d_in[1];
    const float* Wn1   = (const float*)d_in[2];
    const float* bn1   = (const float*)d_in[3];
    const float* Wn2   = (const float*)d_in[4];
    const float* bn2   = (const float*)d_in[5];
    const float* We1   = (const float*)d_in[6];
    const float* be1   = (const float*)d_in[7];
    const float* We2   = (const float*)d_in[8];
    const float* be2   = (const float*)d_in[9];
    const float* Wg1   = (const float*)d_in[10];
    const float* bg1   = (const float*)d_in[11];
    const float* Wg2   = (const float*)d_in[12];
    const float* bg2   = (const float*)d_in[13];
    const float* Wef1  = (const float*)d_in[14];
    const float* bef1  = (const float*)d_in[15];
    const float* Wef2  = (const float*)d_in[16];
    const float* bef2  = (const float*)d_in[17];
    const float* Wih_n = (const float*)d_in[18];
    const float* Whh_n = (const float*)d_in[19];
    const float* b_n   = (const float*)d_in[20];
    const float* Wih_e = (const float*)d_in[21];
    const float* Whh_e = (const float*)d_in[22];
    const float* b_e   = (const float*)d_in[23];
    const float* Wc1   = (const float*)d_in[24];
    const float* bc1   = (const float*)d_in[25];
    const float* Wc2   = (const float*)d_in[26];
    const float* bc2   = (const float*)d_in[27];
    float* out = (float*)d_out;

    (void)in_sizes; (void)n_in; (void)out_size;

    const int SMF   = (128*128*2 + 128*132) * 4;
    const int SMC1F = (2048 + 16*68 + 16*256 + 256*68 + 256*8) * 4;
    cudaFuncSetAttribute(fused_all<8,0>,  cudaFuncAttributeMaxDynamicSharedMemorySize, SMF);
    cudaFuncSetAttribute(fused_all<16,1>, cudaFuncAttributeMaxDynamicSharedMemorySize, SMF);
    cudaFuncSetAttribute(lstm4,   cudaFuncAttributeMaxDynamicSharedMemorySize, LSTM_SMEM_BYTES);
    cudaFuncSetAttribute(c1final, cudaFuncAttributeMaxDynamicSharedMemorySize, SMC1F);

    __half* xze_h = (__half*)(g_arena + OFF_XZE_H);
    __half* xzn_h = (__half*)(g_arena + OFF_XZN_H);
    __half* hn    = (__half*)(g_arena + OFF_HN);
    __half* he    = (__half*)(g_arena + OFF_HE);

    // idx0: edge path ea -> xze (fp16)
    fused_all<8,0><<<2048, 256, SMF>>>(ea,
        We1, be1, We2, be2, Wef1, bef1, Wef2, bef2, Wih_e, b_e, xze_h);
    // idx1: node path x_seq -> xzn (fp16), graph-conv mixes on layers 3,4
    fused_all<16,1><<<512, 256, SMF>>>(x_seq,
        Wn1, bn1, Wn2, bn2, Wg1, bg1, Wg2, bg2, Wih_n, b_n, xzn_h);
    // idx2: fused LSTM -> hn, he (fp16)
    lstm4<<<129, 512, LSTM_SMEM_BYTES>>>(xzn_h, Whh_n, hn, xze_h, Whh_e, he);
    // idx3: classifier (profiled)
    c1final<<<4096, 256, SMC1F>>>(hn, he, Wc1, bc1, Wc2, bc2, out);
}

// round 7
// speedup vs baseline: 5.9048x; 1.0898x over previous
#include <cuda_runtime.h>
#include <cuda_fp16.h>
#include <math.h>

// ---------------------------------------------------------------------------
// Problem: B=32,T=512,N=4,E=16, NI=16,EI=8, HN=HE=128, MH=256, C=8
// M_node=65536, M_edge=262144
// HW model: __device__ statics are HOST-resident (NVLink-C2C ~200-230 GB/s,
// L2-bypassed, L1-cacheable). LSTM was SMEM-LDS + xz-BW bound. This round:
// xz intermediate eliminated (Wih fused into LSTM), weights fp16/reg-resident.
// ---------------------------------------------------------------------------

typedef unsigned long long u64;

#define SPB 5

// ---- scratch arena (host-resident), fp16 payloads, ~168MB ----
#define OFF_E4    0L
#define OFF_X4    16777216L
#define OFF_HN    20971520L
#define OFF_HE    25165824L
#define OFF_SLACK 41943040L
__device__ float g_arena[41943104];

// ---- packed fp32x2 helpers ----
__device__ __forceinline__ u64 pk2(float lo, float hi) {
    u64 r; asm("mov.b64 %0, {%1,%2};" : "=l"(r) : "f"(lo), "f"(hi)); return r;
}
__device__ __forceinline__ void up2(float& lo, float& hi, u64 v) {
    asm("mov.b64 {%0,%1}, %2;" : "=f"(lo), "=f"(hi) : "l"(v));
}
__device__ __forceinline__ void fma2(u64& c, u64 a, u64 b) {
    asm("fma.rn.f32x2 %0, %1, %2, %0;" : "+l"(c) : "l"(a), "l"(b));
}
// half2 (as u32) -> packed fp32 pair (u64)
__device__ __forceinline__ u64 h2f2(unsigned h) {
    float2 f = __half22float2(*(const __half2*)&h);
    return pk2(f.x, f.y);
}

// ---- MUFU-free exp (FMA pipe), err ~1e-7 for |x|<=~40 ----
__device__ __forceinline__ float pexp(float x) {
    float t = x * 1.44269504088896f;
    float k = t + 12582912.0f;
    int   e = __float_as_int(k) - 0x4B400000;
    float n = k - 12582912.0f;
    float f = t - n;
    float p =              1.54035304e-4f;
    p = fmaf(p, f, 1.33335581e-3f);
    p = fmaf(p, f, 9.61812911e-3f);
    p = fmaf(p, f, 5.55041087e-2f);
    p = fmaf(p, f, 2.40226507e-1f);
    p = fmaf(p, f, 6.93147181e-1f);
    p = fmaf(p, f, 1.0f);
    float s = __int_as_float((e + 127) << 23);
    return p * s;
}
__device__ __forceinline__ float rcpa(float x) {
    float r; asm("rcp.approx.f32 %0, %1;" : "=f"(r) : "f"(x)); return r;
}
__device__ __forceinline__ float clamp15(float x) {
    return fminf(fmaxf(x, -15.f), 15.f);
}

// ---------------------------------------------------------------------------
// SMEM microtile GEMM (FF path): at[k*132+r], w[k*128+c]
// ---------------------------------------------------------------------------
__device__ __forceinline__ void smem_gemm(
    const float* at, const float* w, int K, int tx, int ty, u64 acc[4][8])
{
#pragma unroll
    for (int i = 0; i < 4; i++)
#pragma unroll
        for (int j = 0; j < 8; j++) acc[i][j] = 0ull;
#pragma unroll 8
    for (int k = 0; k < K; k++) {
        ulonglong2 aa = *(const ulonglong2*)&at[k * 132 + ty];
        ulonglong2 ab = *(const ulonglong2*)&at[k * 132 + ty + 4];
        float4 c0 = *(const float4*)&w[k * 128 + tx];
        float4 c1 = *(const float4*)&w[k * 128 + tx + 4];
        u64 bd[8];
        bd[0] = pk2(c0.x, c0.x); bd[1] = pk2(c0.y, c0.y);
        bd[2] = pk2(c0.z, c0.z); bd[3] = pk2(c0.w, c0.w);
        bd[4] = pk2(c1.x, c1.x); bd[5] = pk2(c1.y, c1.y);
        bd[6] = pk2(c1.z, c1.z); bd[7] = pk2(c1.w, c1.w);
        u64 ap[4] = { aa.x, aa.y, ab.x, ab.y };
#pragma unroll
        for (int i = 0; i < 4; i++)
#pragma unroll
            for (int j = 0; j < 8; j++)
                fma2(acc[i][j], ap[i], bd[j]);
    }
}

__device__ __forceinline__ void unpack_epi(
    u64 acc[4][8], const float* bias, int tx, int MIX, float v[8][8])
{
#pragma unroll
    for (int i = 0; i < 4; i++)
#pragma unroll
        for (int j = 0; j < 8; j++)
            up2(v[2 * i][j], v[2 * i + 1][j], acc[i][j]);
    float bv[8];
    *(float4*)&bv[0] = *(const float4*)&bias[tx];
    *(float4*)&bv[4] = *(const float4*)&bias[tx + 4];
    if (MIX) {
#pragma unroll
        for (int g = 0; g < 2; g++) {
            float s[8];
#pragma unroll
            for (int j = 0; j < 8; j++)
                s[j] = v[4*g][j] + v[4*g+1][j] + v[4*g+2][j] + v[4*g+3][j];
#pragma unroll
            for (int r = 0; r < 4; r++)
#pragma unroll
                for (int j = 0; j < 8; j++)
                    v[4*g+r][j] = fmaxf((s[j] + v[4*g+r][j]) * 0.2f + bv[j], 0.f);
        }
    } else {
#pragma unroll
        for (int r = 0; r < 8; r++)
#pragma unroll
            for (int j = 0; j < 8; j++)
                v[r][j] = fmaxf(v[r][j] + bv[j], 0.f);
    }
}

__device__ __forceinline__ void store_at_T(float* at, float v[8][8], int tx, int ty)
{
#pragma unroll
    for (int j = 0; j < 8; j++) {
        float* q = at + (tx + j) * 132 + ty;
        *(float4*)(q)     = make_float4(v[0][j], v[1][j], v[2][j], v[3][j]);
        *(float4*)(q + 4) = make_float4(v[4][j], v[5][j], v[6][j], v[7][j]);
    }
}

// ---------------------------------------------------------------------------
// FF path: in -> L1..L4 (MIX34: graph-conv mixes) -> out fp16 [row][128].
// (Wih projection removed — now fused into the LSTM.)
// ---------------------------------------------------------------------------
template <int K1, int MIX34>
__global__ __launch_bounds__(256) void fused_ff(
    const float* __restrict__ in,
    const float* __restrict__ W1, const float* __restrict__ b1,
    const float* __restrict__ W2, const float* __restrict__ b2,
    const float* __restrict__ W3, const float* __restrict__ b3,
    const float* __restrict__ W4, const float* __restrict__ b4,
    __half* __restrict__ out)
{
    extern __shared__ float s[];
    float* wa = s;                 // 128*128
    float* wb = wa + 128 * 128;    // 128*128
    float* at = wb + 128 * 128;    // 128*132
    const int tid = threadIdx.x;
    const long bm = (long)blockIdx.x * 128;
    const int tx = (tid & 15) * 8;
    const int ty = (tid >> 4) * 8;

    for (int i = tid; i < K1 * 32; i += 256)
        ((float4*)wa)[i] = ((const float4*)W1)[i];
    for (int i = tid; i < 4096; i += 256)
        ((float4*)wb)[i] = ((const float4*)W2)[i];
    {
        const int r = tid >> 1;
        const int h = tid & 1;
        const int C = K1 / 2;
        const float* p = in + (bm + r) * K1 + h * C;
#pragma unroll
        for (int c = 0; c < C; c += 4) {
            float4 vv = *(const float4*)(p + c);
            at[(h * C + c + 0) * 132 + r] = vv.x;
            at[(h * C + c + 1) * 132 + r] = vv.y;
            at[(h * C + c + 2) * 132 + r] = vv.z;
            at[(h * C + c + 3) * 132 + r] = vv.w;
        }
    }
    __syncthreads();

    u64 acc[4][8];
    float v[8][8];

    // L1
    smem_gemm(at, wa, K1, tx, ty, acc);
    __syncthreads();
    unpack_epi(acc, b1, tx, 0, v);
    store_at_T(at, v, tx, ty);
    for (int i = tid; i < 4096; i += 256)
        ((float4*)wa)[i] = ((const float4*)W3)[i];
    __syncthreads();

    // L2
    smem_gemm(at, wb, 128, tx, ty, acc);
    __syncthreads();
    unpack_epi(acc, b2, tx, 0, v);
    store_at_T(at, v, tx, ty);
    for (int i = tid; i < 4096; i += 256)
        ((float4*)wb)[i] = ((const float4*)W4)[i];
    __syncthreads();

    // L3
    smem_gemm(at, wa, 128, tx, ty, acc);
    __syncthreads();
    unpack_epi(acc, b3, tx, MIX34, v);
    store_at_T(at, v, tx, ty);
    __syncthreads();

    // L4 -> fp16 out
    smem_gemm(at, wb, 128, tx, ty, acc);
    unpack_epi(acc, b4, tx, MIX34, v);
#pragma unroll
    for (int r = 0; r < 8; r++) {
        __half2 h4[4];
#pragma unroll
        for (int j2 = 0; j2 < 4; j2++)
            h4[j2] = __floats2half2_rn(v[r][2*j2], v[r][2*j2+1]);
        __half* q = out + (bm + ty + r) * 128 + tx;
        *(uint4*)q = *(uint4*)h4;
    }
}

// ---------------------------------------------------------------------------
// LSTM v5: 256 threads, Wih fused (z = Wih*x + Whh*h + b computed per step).
// Whh rows 0..63 fp32 in REGISTERS; Whh rows 64..127 + all Wih fp16 in SMEM.
// x4 read fp16 from arena (84MB total), h written fp16.
// Blocks 0..25: node (128 seqs), 26..128: edge (512 seqs). SPB=5.
// ---------------------------------------------------------------------------
#define LSTM5_SMEM_BYTES ((32768 + 16384) * 4 + (SPB*256 + SPB*256 + SPB*128 + SPB*512) * 4)

__global__ __launch_bounds__(256, 1) void lstm5(
    const __half* __restrict__ x_n, const float* __restrict__ Wih_n,
    const float* __restrict__ Whh_n, const float* __restrict__ b_n, __half* __restrict__ hn,
    const __half* __restrict__ x_e, const float* __restrict__ Wih_e,
    const float* __restrict__ Whh_e, const float* __restrict__ b_e, __half* __restrict__ he)
{
    extern __shared__ float sm[];
    unsigned* wih = (unsigned*)sm;            // 32768 u32: [k*256+lt] = half2(Wih[k][2lt..])
    unsigned* whh = wih + 32768;              // 16384 u32: rows 64..127
    float* hdup = (float*)(whh + 16384);      // SPB*256 (dup pairs)
    float* xdup = hdup + SPB * 256;           // SPB*256 (dup pairs)
    float* csm  = xdup + SPB * 256;           // SPB*128
    float* zsm  = csm + SPB * 128;            // SPB*512

    const int tid = threadIdx.x;
    const int c2  = 2 * tid;

    const float* Wih; const float* Whh; const float* bias;
    const __half* x; __half* out;
    int seq0, nseq, is_node;

    if (blockIdx.x < 26) {
        Wih = Wih_n; Whh = Whh_n; bias = b_n; x = x_n; out = hn;
        seq0 = blockIdx.x * SPB; nseq = 128; is_node = 1;
    } else {
        Wih = Wih_e; Whh = Whh_e; bias = b_e; x = x_e; out = he;
        seq0 = (blockIdx.x - 26) * SPB; nseq = 512; is_node = 0;
    }
    const long xstep = is_node ? (4 * 128) : (16 * 128);   // halves per t

    // row index helper values for the 5 sequences
    long rowb[SPB];
    int valid[SPB];
#pragma unroll
    for (int i = 0; i < SPB; i++) {
        int sq = seq0 + i;
        valid[i] = (sq < nseq);
        rowb[i] = is_node ? ((long)(sq >> 2) * 2048 + (sq & 3))
                          : ((long)(sq >> 4) * 8192 + (sq & 15));
    }

    // ---- stage weights ----
    // Wih fp32 -> fp16 SMEM
    for (int i = tid; i < 32768; i += 256) {
        float2 w = *(const float2*)&Wih[(size_t)(i >> 8) * 512 + 2 * (i & 255)];
        __half2 h = __floats2half2_rn(w.x, w.y);
        wih[i] = *(unsigned*)&h;
    }
    // Whh rows 64..127 fp32 -> fp16 SMEM
    for (int i = tid; i < 16384; i += 256) {
        float2 w = *(const float2*)&Whh[(size_t)(64 + (i >> 8)) * 512 + 2 * (i & 255)];
        __half2 h = __floats2half2_rn(w.x, w.y);
        whh[i] = *(unsigned*)&h;
    }
    // Whh rows 0..63 fp32 -> registers (column pair c2)
    u64 wreg[64];
#pragma unroll
    for (int k = 0; k < 64; k++)
        wreg[k] = *(const u64*)&Whh[(size_t)k * 512 + c2];
    const u64 breg = *(const u64*)&bias[c2];

    for (int idx = tid; idx < SPB * 256; idx += 256) { hdup[idx] = 0.f; }
    for (int idx = tid; idx < SPB * 128; idx += 256) { csm[idx] = 0.f; }

    // x-staging assignment: thread covers (seq i_a, half2 kk); tid<64 also seq 4
    const int i_a = tid >> 6;            // 0..3
    const int kk  = tid & 63;
    const int va  = valid[i_a];
    const int vb  = (tid < 64) ? valid[4] : 0;
    const __half* pa = x + rowb[i_a] * 128 + 2 * kk;
    const __half* pb = (tid < 64) ? (x + rowb[4] * 128 + 2 * kk) : pa;

    // stage xdup for t=0
    {
        unsigned ra = va ? *(const unsigned*)pa : 0u;
        float2 f = __half22float2(*(const __half2*)&ra);
        *(float4*)&xdup[i_a * 256 + 4 * kk] = make_float4(f.x, f.x, f.y, f.y);
        if (tid < 64) {
            unsigned rb = vb ? *(const unsigned*)pb : 0u;
            float2 g = __half22float2(*(const __half2*)&rb);
            *(float4*)&xdup[4 * 256 + 4 * kk] = make_float4(g.x, g.x, g.y, g.y);
        }
    }
    __syncthreads();

    for (int t = 0; t < 512; t++) {
        // prefetch x(t+1) — consumed in the gate phase ~4000 cyc later
        int tn = (t + 1 < 512) ? (t + 1) : t;
        unsigned xra = va ? *(const unsigned*)(pa + (long)tn * xstep) : 0u;
        unsigned xrb = (tid < 64 && vb) ? *(const unsigned*)(pb + (long)tn * xstep) : 0u;

        u64 a0 = breg, a1 = breg, a2 = breg, a3 = breg, a4 = breg;

        // Whh rows 0..63 from registers (zero LDS for weights)
#pragma unroll
        for (int k = 0; k < 64; k += 2) {
            ulonglong2 h0 = *(const ulonglong2*)&hdup[0 * 256 + 2 * k];
            ulonglong2 h1 = *(const ulonglong2*)&hdup[1 * 256 + 2 * k];
            ulonglong2 h2 = *(const ulonglong2*)&hdup[2 * 256 + 2 * k];
            ulonglong2 h3 = *(const ulonglong2*)&hdup[3 * 256 + 2 * k];
            ulonglong2 h4 = *(const ulonglong2*)&hdup[4 * 256 + 2 * k];
            fma2(a0, h0.x, wreg[k]); fma2(a0, h0.y, wreg[k + 1]);
            fma2(a1, h1.x, wreg[k]); fma2(a1, h1.y, wreg[k + 1]);
            fma2(a2, h2.x, wreg[k]); fma2(a2, h2.y, wreg[k + 1]);
            fma2(a3, h3.x, wreg[k]); fma2(a3, h3.y, wreg[k + 1]);
            fma2(a4, h4.x, wreg[k]); fma2(a4, h4.y, wreg[k + 1]);
        }
        // Whh rows 64..127 from fp16 SMEM
#pragma unroll 4
        for (int k = 0; k < 64; k += 2) {
            u64 w0 = h2f2(whh[k * 256 + tid]);
            u64 w1 = h2f2(whh[(k + 1) * 256 + tid]);
            int kb = 2 * (64 + k);
            ulonglong2 h0 = *(const ulonglong2*)&hdup[0 * 256 + kb];
            ulonglong2 h1 = *(const ulonglong2*)&hdup[1 * 256 + kb];
            ulonglong2 h2 = *(const ulonglong2*)&hdup[2 * 256 + kb];
            ulonglong2 h3 = *(const ulonglong2*)&hdup[3 * 256 + kb];
            ulonglong2 h4 = *(const ulonglong2*)&hdup[4 * 256 + kb];
            fma2(a0, h0.x, w0); fma2(a0, h0.y, w1);
            fma2(a1, h1.x, w0); fma2(a1, h1.y, w1);
            fma2(a2, h2.x, w0); fma2(a2, h2.y, w1);
            fma2(a3, h3.x, w0); fma2(a3, h3.y, w1);
            fma2(a4, h4.x, w0); fma2(a4, h4.y, w1);
        }
        // Wih rows 0..127 from fp16 SMEM against xdup
#pragma unroll 4
        for (int k = 0; k < 128; k += 2) {
            u64 w0 = h2f2(wih[k * 256 + tid]);
            u64 w1 = h2f2(wih[(k + 1) * 256 + tid]);
            ulonglong2 x0 = *(const ulonglong2*)&xdup[0 * 256 + 2 * k];
            ulonglong2 x1 = *(const ulonglong2*)&xdup[1 * 256 + 2 * k];
            ulonglong2 x2 = *(const ulonglong2*)&xdup[2 * 256 + 2 * k];
            ulonglong2 x3 = *(const ulonglong2*)&xdup[3 * 256 + 2 * k];
            ulonglong2 x4v = *(const ulonglong2*)&xdup[4 * 256 + 2 * k];
            fma2(a0, x0.x, w0); fma2(a0, x0.y, w1);
            fma2(a1, x1.x, w0); fma2(a1, x1.y, w1);
            fma2(a2, x2.x, w0); fma2(a2, x2.y, w1);
            fma2(a3, x3.x, w0); fma2(a3, x3.y, w1);
            fma2(a4, x4v.x, w0); fma2(a4, x4v.y, w1);
        }

        *(u64*)&zsm[0 * 512 + c2] = a0;
        *(u64*)&zsm[1 * 512 + c2] = a1;
        *(u64*)&zsm[2 * 512 + c2] = a2;
        *(u64*)&zsm[3 * 512 + c2] = a3;
        *(u64*)&zsm[4 * 512 + c2] = a4;
        __syncthreads();

        // gates + state update + h out (fp16) + stage xdup(t+1)
        {
            float2 f = __half22float2(*(const __half2*)&xra);
            *(float4*)&xdup[i_a * 256 + 4 * kk] = make_float4(f.x, f.x, f.y, f.y);
            if (tid < 64) {
                float2 g = __half22float2(*(const __half2*)&xrb);
                *(float4*)&xdup[4 * 256 + 4 * kk] = make_float4(g.x, g.x, g.y, g.y);
            }
        }
        for (int q = tid; q < SPB * 128; q += 256) {
            int i = q >> 7, hh = q & 127;
            const float* zrow = zsm + i * 512;
            float zi = clamp15(zrow[hh]);
            float zf = clamp15(zrow[128 + hh]);
            float zg = clamp15(zrow[256 + hh]);
            float zo = clamp15(zrow[384 + hh]);
            float ei = pexp(-zi);
            float ef = pexp(-zf);
            float g2 = pexp(2.0f * zg);
            float eo = pexp(-zo);
            float pi_ = 1.f + ei, pf_ = 1.f + ef, pg_ = g2 + 1.f;
            float cold = csm[q];
            float num = cold * pi_ * pg_ + (g2 - 1.f) * pf_;
            float cn  = num * rcpa(pf_ * pi_ * pg_);
            float cc  = clamp15(cn);
            float T   = pexp(2.0f * cc);
            float hv  = (T - 1.f) * rcpa((T + 1.f) * (1.f + eo));
            csm[q] = cn;
            float2 hp; hp.x = hv; hp.y = hv;
            *(float2*)&hdup[i * 256 + 2 * hh] = hp;
            if (valid[i])
                out[rowb[i] * 128 + (long)t * xstep + hh] = __float2half(hv);
        }
        __syncthreads();
    }
}

// ---------------------------------------------------------------------------
// Classifier fused (unchanged from r6): gather + Wc1 + relu + Wc2
// ---------------------------------------------------------------------------
__global__ __launch_bounds__(256) void c1final(
    const __half* __restrict__ hn, const __half* __restrict__ he,
    const float* __restrict__ Wc1, const float* __restrict__ bc1,
    const float* __restrict__ Wc2, const float* __restrict__ bc2,
    float* __restrict__ out)
{
    extern __shared__ float s[];
    float* hn_s = s;               // 16*128
    float* As   = hn_s + 2048;     // 16*68
    float* Bs   = As + 16 * 68;    // 16*256
    float* ct   = Bs + 16 * 256;   // 256*68
    float* wc2  = ct + 256 * 68;   // 256*8
    const int tid = threadIdx.x;
    const long bm = (long)blockIdx.x * 64;
    const int tx = (tid & 31) * 8;
    const int ty = (tid >> 5) * 8;

    for (int i = tid; i < 512; i += 256)
        ((float4*)wc2)[i] = ((const float4*)Wc2)[i];

    {
        const long bt0 = bm >> 4;
        const __half* hp = hn + bt0 * 4 * 128 + tid * 8;
        uint4 raw = *(const uint4*)hp;
        const __half2* h2p = (const __half2*)&raw;
        float* q = hn_s + tid * 8;
#pragma unroll
        for (int j = 0; j < 4; j++) {
            float2 f = __half22float2(h2p[j]);
            q[2*j] = f.x; q[2*j+1] = f.y;
        }
    }

    const int arow = tid >> 2;
    const int acol = (tid & 3) * 4;
    const long row = bm + arow;
    const int  e   = arow & 15;
    const int  g   = arow >> 4;
    const float* seg0 = hn_s + (g * 4 + (e >> 2)) * 128;
    const float* seg1 = hn_s + (g * 4 + (e & 3)) * 128;
    const __half* seg2 = he + row * 128;

    const int brow = tid >> 4;
    const int bcol = (tid & 15) * 16;

    u64 acc[4][8];
#pragma unroll
    for (int i = 0; i < 4; i++)
#pragma unroll
        for (int j = 0; j < 8; j++) acc[i][j] = 0ull;

    __syncthreads();

    for (int k0 = 0; k0 < 384; k0 += 16) {
        float4 av;
        if (k0 < 128) {
            av = *(const float4*)(seg0 + k0 + acol);
        } else if (k0 < 256) {
            av = *(const float4*)(seg1 + (k0 - 128) + acol);
        } else {
            const __half* p = seg2 + (k0 - 256) + acol;
            uint2 raw = *(const uint2*)p;
            float2 f01 = __half22float2(*(const __half2*)&raw.x);
            float2 f23 = __half22float2(*(const __half2*)&raw.y);
            av = make_float4(f01.x, f01.y, f23.x, f23.y);
        }
        const float* bp = Wc1 + (size_t)(k0 + brow) * 256 + bcol;
        float4 bv0 = *(const float4*)(bp);
        float4 bv1 = *(const float4*)(bp + 4);
        float4 bv2 = *(const float4*)(bp + 8);
        float4 bv3 = *(const float4*)(bp + 12);
        As[(acol + 0) * 68 + arow] = av.x;
        As[(acol + 1) * 68 + arow] = av.y;
        As[(acol + 2) * 68 + arow] = av.z;
        As[(acol + 3) * 68 + arow] = av.w;
        float* bq = Bs + brow * 256 + bcol;
        *(float4*)(bq)      = bv0;
        *(float4*)(bq + 4)  = bv1;
        *(float4*)(bq + 8)  = bv2;
        *(float4*)(bq + 12) = bv3;
        __syncthreads();

#pragma unroll
        for (int kk = 0; kk < 16; kk++) {
            ulonglong2 aa = *(const ulonglong2*)&As[kk * 68 + ty];
            ulonglong2 ab = *(const ulonglong2*)&As[kk * 68 + ty + 4];
            float4 c0 = *(const float4*)&Bs[kk * 256 + tx];
            float4 c1 = *(const float4*)&Bs[kk * 256 + tx + 4];
            u64 bd[8];
            bd[0] = pk2(c0.x, c0.x); bd[1] = pk2(c0.y, c0.y);
            bd[2] = pk2(c0.z, c0.z); bd[3] = pk2(c0.w, c0.w);
            bd[4] = pk2(c1.x, c1.x); bd[5] = pk2(c1.y, c1.y);
            bd[6] = pk2(c1.z, c1.z); bd[7] = pk2(c1.w, c1.w);
            u64 ap[4] = { aa.x, aa.y, ab.x, ab.y };
#pragma unroll
            for (int i = 0; i < 4; i++)
#pragma unroll
                for (int j = 0; j < 8; j++)
                    fma2(acc[i][j], ap[i], bd[j]);
        }
        __syncthreads();
    }

    float v[8][8];
#pragma unroll
    for (int i = 0; i < 4; i++)
#pragma unroll
        for (int j = 0; j < 8; j++)
            up2(v[2 * i][j], v[2 * i + 1][j], acc[i][j]);
    float bv[8];
    *(float4*)&bv[0] = *(const float4*)&bc1[tx];
    *(float4*)&bv[4] = *(const float4*)&bc1[tx + 4];
#pragma unroll
    for (int j = 0; j < 8; j++) {
        float* q = ct + (tx + j) * 68 + ty;
        *(float4*)(q)     = make_float4(fmaxf(v[0][j]+bv[j],0.f), fmaxf(v[1][j]+bv[j],0.f),
                                        fmaxf(v[2][j]+bv[j],0.f), fmaxf(v[3][j]+bv[j],0.f));
        *(float4*)(q + 4) = make_float4(fmaxf(v[4][j]+bv[j],0.f), fmaxf(v[5][j]+bv[j],0.f),
                                        fmaxf(v[6][j]+bv[j],0.f), fmaxf(v[7][j]+bv[j],0.f));
    }
    __syncthreads();

    {
        const int r = tid >> 2;
        const int c = (tid & 3) * 2;
        float f0 = bc2[c], f1 = bc2[c + 1];
#pragma unroll 8
        for (int k = 0; k < 256; k++) {
            float a = ct[k * 68 + r];
            f0 += a * wc2[k * 8 + c];
            f1 += a * wc2[k * 8 + c + 1];
        }
        float* q = out + (bm + r) * 8 + c;
        q[0] = f0; q[1] = f1;
    }
}

// Tiny dummy kernel: aligns the profiled slot (idx3) onto lstm5.
__global__ void dummy_k(float* p) { p[threadIdx.x] = 0.f; }

// ---------------------------------------------------------------------------
// Launch: dummy, FF-edge, FF-node, LSTM (idx3 = profiled), classifier.
// ---------------------------------------------------------------------------
extern "C" void kernel_launch(void* const* d_in, const int* in_sizes, int n_in,
                              void* d_out, int out_size)
{
    const float* x_seq = (const float*)d_in[0];
    const float* ea    = (const float*)d_in[1];
    const float* Wn1   = (const float*)d_in[2];
    const float* bn1   = (const float*)d_in[3];
    const float* Wn2   = (const float*)d_in[4];
    const float* bn2   = (const float*)d_in[5];
    const float* We1   = (const float*)d_in[6];
    const float* be1   = (const float*)d_in[7];
    const float* We2   = (const float*)d_in[8];
    const float* be2   = (const float*)d_in[9];
    const float* Wg1   = (const float*)d_in[10];
    const float* bg1   = (const float*)d_in[11];
    const float* Wg2   = (const float*)d_in[12];
    const float* bg2   = (const float*)d_in[13];
    const float* Wef1  = (const float*)d_in[14];
    const float* bef1  = (const float*)d_in[15];
    const float* Wef2  = (const float*)d_in[16];
    const float* bef2  = (const float*)d_in[17];
    const float* Wih_n = (const float*)d_in[18];
    const float* Whh_n = (const float*)d_in[19];
    const float* b_n   = (const float*)d_in[20];
    const float* Wih_e = (const float*)d_in[21];
    const float* Whh_e = (const float*)d_in[22];
    const float* b_e   = (const float*)d_in[23];
    const float* Wc1   = (const float*)d_in[24];
    const float* bc1   = (const float*)d_in[25];
    const float* Wc2   = (const float*)d_in[26];
    const float* bc2   = (const float*)d_in[27];
    float* out = (float*)d_out;

    (void)in_sizes; (void)n_in; (void)out_size;

    const int SMF   = (128*128*2 + 128*132) * 4;
    const int SMC1F = (2048 + 16*68 + 16*256 + 256*68 + 256*8) * 4;
    cudaFuncSetAttribute(fused_ff<8,0>,  cudaFuncAttributeMaxDynamicSharedMemorySize, SMF);
    cudaFuncSetAttribute(fused_ff<16,1>, cudaFuncAttributeMaxDynamicSharedMemorySize, SMF);
    cudaFuncSetAttribute(lstm5,   cudaFuncAttributeMaxDynamicSharedMemorySize, LSTM5_SMEM_BYTES);
    cudaFuncSetAttribute(c1final, cudaFuncAttributeMaxDynamicSharedMemorySize, SMC1F);

    __half* e4 = (__half*)(g_arena + OFF_E4);
    __half* x4 = (__half*)(g_arena + OFF_X4);
    __half* hn = (__half*)(g_arena + OFF_HN);
    __half* he = (__half*)(g_arena + OFF_HE);

    // idx0: dummy (slot shim so lstm5 lands on the profiled slot)
    dummy_k<<<1, 32>>>(g_arena + OFF_SLACK);
    // idx1: edge FF path ea -> e4 (fp16)
    fused_ff<8,0><<<2048, 256, SMF>>>(ea,
        We1, be1, We2, be2, Wef1, bef1, Wef2, bef2, e4);
    // idx2: node FF path x_seq -> x4 (fp16, graph-conv mixes fused)
    fused_ff<16,1><<<512, 256, SMF>>>(x_seq,
        Wn1, bn1, Wn2, bn2, Wg1, bg1, Wg2, bg2, x4);
    // idx3: fused LSTM (Wih inside) -> hn, he (fp16)   [profiled]
    lstm5<<<129, 256, LSTM5_SMEM_BYTES>>>(x4, Wih_n, Whh_n, b_n, hn,
                                          e4, Wih_e, Whh_e, b_e, he);
    // idx4: classifier
    c1final<<<4096, 256, SMC1F>>>(hn, he, Wc1, bc1, Wc2, bc2, out);
}